// round 8
// baseline (speedup 1.0000x reference)
#include <cuda_runtime.h>
#include <cuda_fp16.h>
#include <cstdint>

// ---------------------------------------------------------------------------
// MoE (AriaExperts): top-2 routing + grouped tcgen05 f16 GEMM (SwiGLU fused)
// tokens=2048, hidden=1024, inter=2048, experts=8, topk=2
//
// R8: launch list compressed to 6 (gemm_fc1 at ncu-profiled index 3);
// BN=128 per CTA (halves A re-reads); FC2 atomic-free (scratch + combine).
// tcgen05 MMA config (K-major SW128 SS, idesc 0x8100010, M=128/N=64 regions)
// unchanged from the validated R6/R7 kernels.
// ---------------------------------------------------------------------------

#if defined(__CUDA_ARCH__) && \
    (defined(__CUDA_ARCH_FEAT_SM103_ALL) || \
     (defined(__CUDA_ARCH_SPECIFIC__)) || \
     (defined(__CUDA_ARCH_FAMILY_SPECIFIC__)))
#define USE_TC 1
#else
#define USE_TC 0
#endif

#define NT     2048
#define HID    1024
#define INTERD 2048
#define NE     8
#define TK     2
#define NP     (NT*TK)
#define NPP    (NP + 256)    // BM=256 tile overrun padding

// ---- device scratch ----
__device__ __align__(16) __half g_Xp  [NPP * HID];
__device__ __align__(16) __half g_Act [NPP * INTERD];
__device__ __align__(16) float  g_Out2[NPP * HID];              // FC2 results per pair
__device__ __align__(16) __half g_W1h[NE * 2 * INTERD * HID];   // [E][4096][1024] k-contig
__device__ __align__(16) __half g_W2h[NE * HID * INTERD];       // [E][1024][2048] k-contig
__device__ int   g_counts[NE];
__device__ int   g_fill[NE];
__device__ int   g_offsets[NE + 1];
__device__ int   g_tok_e[NT * TK];
__device__ float g_tok_s[NT * TK];
__device__ int   g_tok_pos[NT * TK];

#define SW128(o) ((o) ^ (((o) >> 3) & 0x70))

// ---------------------------------------------------------------------------
// conv: weight transpose + fp32->fp16  (in [e][K][N] f32 -> out [e][N][K] f16)
// 32x32 tiles, block (32,8). zeroFlag: clear routing counters (conv1 only).
// routeFlag: blocks (x==0,y==0) additionally route 256 tokens each (conv2).
// ---------------------------------------------------------------------------
__global__ void convT_kernel(const float* __restrict__ in, __half* __restrict__ out,
                             int K, int N, int zeroFlag, int routeFlag,
                             const float* __restrict__ logits) {
    __shared__ float tile[32][33];
    const int e  = blockIdx.z;
    const int n0 = blockIdx.x * 32, k0 = blockIdx.y * 32;
    const float* ip = in  + (size_t)e * K * N;
    __half*      op = out + (size_t)e * N * K;
    const int tx = threadIdx.x, ty = threadIdx.y;
#pragma unroll
    for (int i = 0; i < 4; i++)
        tile[ty + i * 8][tx] = ip[(size_t)(k0 + ty + i * 8) * N + n0 + tx];
    __syncthreads();
#pragma unroll
    for (int i = 0; i < 4; i++)
        op[(size_t)(n0 + ty + i * 8) * K + k0 + tx] =
            __float2half_rn(tile[tx][ty + i * 8]);

    if (zeroFlag && blockIdx.x == 0 && blockIdx.y == 0 && blockIdx.z == 0 &&
        tx == 0 && ty == 0) {
#pragma unroll
        for (int i = 0; i < NE; i++) { g_counts[i] = 0; g_fill[i] = 0; }
    }
    if (routeFlag && blockIdx.x == 0 && blockIdx.y == 0) {
        // 8 z-blocks x 256 threads = 2048 tokens
        int t = blockIdx.z * 256 + ty * 32 + tx;
        float l[NE];
#pragma unroll
        for (int i = 0; i < NE; i++) l[i] = logits[t * NE + i];
        int b0 = 0; float v0 = l[0];
#pragma unroll
        for (int i = 1; i < NE; i++) if (l[i] > v0) { v0 = l[i]; b0 = i; }
        int b1 = -1; float v1 = -1e30f;
#pragma unroll
        for (int i = 0; i < NE; i++) if (i != b0 && l[i] > v1) { v1 = l[i]; b1 = i; }
        float e1  = __expf(v1 - v0);
        float inv = 1.0f / (1.0f + e1);
        g_tok_e[t * 2 + 0] = b0; g_tok_s[t * 2 + 0] = inv;
        g_tok_e[t * 2 + 1] = b1; g_tok_s[t * 2 + 1] = e1 * inv;
        atomicAdd(&g_counts[b0], 1);
        atomicAdd(&g_counts[b1], 1);
    }
}

// ---------------------------------------------------------------------------
// scatter + permute: one block per token-expert pair. Thread 0 claims the
// slot (local prefix over 8 counts + atomic fill), then 128 threads copy
// the token row (fp32->fp16) into the permuted buffer.
// ---------------------------------------------------------------------------
__global__ void scatter_permute_kernel(const float* __restrict__ X) {
    __shared__ int s_pos;
    const int p = blockIdx.x;          // pair id
    const int t = p >> 1;
    if (threadIdx.x == 0) {
        int e = g_tok_e[p];
        int s = 0, off = 0;
#pragma unroll
        for (int i = 0; i < NE; i++) { if (i == e) off = s; s += g_counts[i]; }
        int pos = off + atomicAdd(&g_fill[e], 1);
        g_tok_pos[p] = pos;
        s_pos = pos;
        if (p == 0) {
            int s2 = 0;
#pragma unroll
            for (int i = 0; i < NE; i++) { g_offsets[i] = s2; s2 += g_counts[i]; }
            g_offsets[NE] = s2;
        }
    }
    __syncthreads();
    const int pos = s_pos;
    const int c = threadIdx.x * 8;
    const float4* s = (const float4*)(X + (size_t)t * HID + c);
    float4 v0 = s[0], v1 = s[1];
    union { __half h[8]; uint4 u; } cv;
    cv.h[0] = __float2half_rn(v0.x); cv.h[1] = __float2half_rn(v0.y);
    cv.h[2] = __float2half_rn(v0.z); cv.h[3] = __float2half_rn(v0.w);
    cv.h[4] = __float2half_rn(v1.x); cv.h[5] = __float2half_rn(v1.y);
    cv.h[6] = __float2half_rn(v1.z); cv.h[7] = __float2half_rn(v1.w);
    *(uint4*)(g_Xp + (size_t)pos * HID + c) = cv.u;
}

// ---------------------------------------------------------------------------
// combine: out[t] = s0 * O2[pos0] + s1 * O2[pos1]   (writes every element)
// ---------------------------------------------------------------------------
__global__ void combine_kernel(float* __restrict__ out) {
    const int t = blockIdx.x;
    const int c = threadIdx.x * 4;
    const int   p0 = g_tok_pos[2 * t],     p1 = g_tok_pos[2 * t + 1];
    const float s0 = g_tok_s[2 * t],       s1 = g_tok_s[2 * t + 1];
    float4 a = *(const float4*)(g_Out2 + (size_t)p0 * HID + c);
    float4 b = *(const float4*)(g_Out2 + (size_t)p1 * HID + c);
    float4 r;
    r.x = s0 * a.x + s1 * b.x;  r.y = s0 * a.y + s1 * b.y;
    r.z = s0 * a.z + s1 * b.z;  r.w = s0 * a.w + s1 * b.w;
    *(float4*)(out + (size_t)t * HID + c) = r;
}

// ---------------------------------------------------------------------------
// tcgen05 helpers (arch-specific pass only)
// ---------------------------------------------------------------------------
#if USE_TC
__device__ __forceinline__ uint32_t elect_one() {
    uint32_t p;
    asm volatile("{\n\t.reg .pred p;\n\telect.sync _|p, 0xFFFFFFFF;\n\t"
                 "selp.b32 %0,1,0,p;\n\t}" : "=r"(p));
    return p;
}
__device__ __forceinline__ void mbar_init(uint32_t a, uint32_t c) {
    asm volatile("mbarrier.init.shared.b64 [%0], %1;" :: "r"(a), "r"(c) : "memory");
}
__device__ __forceinline__ void mbar_wait(uint32_t a, uint32_t par) {
    asm volatile("{\n\t.reg .pred P;\n\tWL_%=:\n\t"
                 "mbarrier.try_wait.parity.acquire.cta.shared::cta.b64 P, [%0], %1, 0x989680;\n\t"
                 "@P bra WD_%=;\n\tbra WL_%=;\n\tWD_%=:\n\t}"
                 :: "r"(a), "r"(par) : "memory");
}
__device__ __forceinline__ void tc_alloc(uint32_t slot, uint32_t n) {
    asm volatile("tcgen05.alloc.cta_group::1.sync.aligned.shared::cta.b32 [%0], %1;"
                 :: "r"(slot), "r"(n) : "memory");
}
__device__ __forceinline__ void tc_relinquish() {
    asm volatile("tcgen05.relinquish_alloc_permit.cta_group::1.sync.aligned;");
}
__device__ __forceinline__ void tc_dealloc(uint32_t t, uint32_t n) {
    asm volatile("tcgen05.dealloc.cta_group::1.sync.aligned.b32 %0, %1;" :: "r"(t), "r"(n));
}
__device__ __forceinline__ void tc_commit(uint32_t mbar) {
    asm volatile("tcgen05.commit.cta_group::1.mbarrier::arrive::one.shared::cluster.b64 [%0];"
                 :: "r"(mbar) : "memory");
}
__device__ __forceinline__ void tc_mma_f16_ss(uint32_t d, uint64_t ad, uint64_t bd,
                                              uint32_t idesc, uint32_t en) {
    asm volatile("{\n\t.reg .pred p;\n\tsetp.ne.u32 p, %4, 0;\n\t"
                 "tcgen05.mma.cta_group::1.kind::f16 [%0], %1, %2, %3, {%5,%5,%5,%5}, p;\n\t}"
                 :: "r"(d), "l"(ad), "l"(bd), "r"(idesc), "r"(en), "r"(0u) : "memory");
}
__device__ __forceinline__ void tc_fence_after()  { asm volatile("tcgen05.fence::after_thread_sync;"  ::: "memory"); }
__device__ __forceinline__ void tc_fence_before() { asm volatile("tcgen05.fence::before_thread_sync;" ::: "memory"); }
__device__ __forceinline__ void tc_wait_ld()      { asm volatile("tcgen05.wait::ld.sync.aligned;"     ::: "memory"); }
__device__ __forceinline__ void fence_async_smem(){ asm volatile("fence.proxy.async.shared::cta;"     ::: "memory"); }
__device__ __forceinline__ void cp16(uint32_t dst, const void* src) {
    asm volatile("cp.async.cg.shared.global [%0], [%1], 16;" :: "r"(dst), "l"(src));
}
__device__ __forceinline__ void cp_commit() { asm volatile("cp.async.commit_group;" ::: "memory"); }
template <int N> __device__ __forceinline__ void cp_wait() {
    asm volatile("cp.async.wait_group %0;" :: "n"(N) : "memory");
}

#define LDTM_X32(r, tmem_addr) \
    asm volatile( \
        "tcgen05.ld.sync.aligned.32x32b.x32.b32 " \
        "{%0, %1, %2, %3, %4, %5, %6, %7, " \
        " %8, %9, %10, %11, %12, %13, %14, %15, " \
        " %16, %17, %18, %19, %20, %21, %22, %23, " \
        " %24, %25, %26, %27, %28, %29, %30, %31}, [%32];" \
        : "=r"((r)[0]),  "=r"((r)[1]),  "=r"((r)[2]),  "=r"((r)[3]), \
          "=r"((r)[4]),  "=r"((r)[5]),  "=r"((r)[6]),  "=r"((r)[7]), \
          "=r"((r)[8]),  "=r"((r)[9]),  "=r"((r)[10]), "=r"((r)[11]), \
          "=r"((r)[12]), "=r"((r)[13]), "=r"((r)[14]), "=r"((r)[15]), \
          "=r"((r)[16]), "=r"((r)[17]), "=r"((r)[18]), "=r"((r)[19]), \
          "=r"((r)[20]), "=r"((r)[21]), "=r"((r)[22]), "=r"((r)[23]), \
          "=r"((r)[24]), "=r"((r)[25]), "=r"((r)[26]), "=r"((r)[27]), \
          "=r"((r)[28]), "=r"((r)[29]), "=r"((r)[30]), "=r"((r)[31]) \
        : "r"(tmem_addr))

// SMEM matrix descriptor: K-major SW128 (LBO=1, SBO=64, version=1, layout=2)
__device__ __forceinline__ uint64_t desc_k(uint32_t a) {
    return 0x4000404000010000ull | ((a >> 4) & 0x3FFF);
}
// idesc kind::f16: c=f32, a/b f16 K-major, N=64, M=128 (validated R6)
#define MMA_IDESC 0x8100010u
#endif // USE_TC

// ---------------------------------------------------------------------------
// Grouped GEMM.  256 threads, BM=256 (2 M=128 blocks), BN=128.
//   MODE 0 (FC1+SwiGLU): grid (16, 16, 8); 128 act cols; B = 4 regions of 64
//                        TMEM: mb*256 + r*64  (512 cols)
//   MODE 1 (FC2):        grid (8, 16, 8);  128 out cols; B = 2 regions of 64
//                        TMEM: mb*128 + r*64  (256 cols); writes g_Out2 fp32
// ---------------------------------------------------------------------------
template <int MODE>
__global__ __launch_bounds__(256)
void moe_gemm_kernel() {
    const int e   = blockIdx.z;
    const int cnt = g_counts[e];
    const int mt  = blockIdx.y;
    if (mt * 256 >= cnt) return;
    const int bn      = blockIdx.x;
    const int rowbase = g_offsets[e] + mt * 256;
    const int rowlim  = g_offsets[e] + cnt;

    constexpr int K = MODE ? INTERD : HID;
    const __half* __restrict__ Ag = MODE ? g_Act : g_Xp;
    const __half* __restrict__ Wh = MODE
        ? (g_W2h + (size_t)e * HID * INTERD)          // [1024][2048] k-contig
        : (g_W1h + (size_t)e * 2 * INTERD * HID);     // [4096][1024] k-contig

    extern __shared__ __align__(1024) char smem[];
    const int tid = threadIdx.x, wid = tid >> 5, lane = tid & 31;

#if USE_TC
    constexpr int KT     = K / 64;
    constexpr int NRg    = MODE ? 2 : 4;              // B regions of 64 n
    constexpr int TCOLS  = MODE ? 256 : 512;
    constexpr int ABYTES = 16384, BBYTES = 8192;
    constexpr int BOFF   = 4 * ABYTES;                // 2 bufs x 2 mblk
    constexpr int CTRL   = BOFF + 2 * NRg * BBYTES;

    uint32_t sbase = (uint32_t)__cvta_generic_to_shared(smem);
    uint32_t mb0 = sbase + CTRL + 8, mb1 = sbase + CTRL + 16;

    if (tid == 0) { mbar_init(mb0, 1); mbar_init(mb1, 1); }
    if (wid == 0) { tc_alloc(sbase + CTRL, TCOLS); tc_relinquish(); }
    __syncthreads();
    uint32_t tmem = *(volatile uint32_t*)(smem + CTRL);

    auto fill_chunk = [&](int j) {
        const int buf = j & 1;
        const int k0  = j * 64;
#pragma unroll
        for (int mb = 0; mb < 2; mb++) {
            uint32_t As = sbase + (buf * 2 + mb) * ABYTES;
            const __half* Ap = Ag + (size_t)(rowbase + mb * 128) * K + k0;
#pragma unroll
            for (int i = 0; i < 4; i++) {
                int u = i * 256 + tid, row = u >> 3, q = u & 7;
                cp16(As + SW128(row * 128 + q * 16), Ap + (size_t)row * K + q * 8);
            }
        }
#pragma unroll
        for (int r = 0; r < NRg; r++) {
            uint32_t Bs = sbase + BOFF + (buf * NRg + r) * BBYTES;
            const int nb = (MODE == 0)
                ? ((r < 2) ? (bn * 128 + r * 64) : (INTERD + bn * 128 + (r - 2) * 64))
                : (bn * 128 + r * 64);
            const __half* Bp = Wh + (size_t)nb * K + k0;
#pragma unroll
            for (int i = 0; i < 2; i++) {
                int u = i * 256 + tid, row = u >> 3, q = u & 7;
                cp16(Bs + SW128(row * 128 + q * 16), Bp + (size_t)row * K + q * 8);
            }
        }
        cp_commit();
    };

    fill_chunk(0);
    for (int kt = 0; kt < KT; kt++) {
        const int buf = kt & 1;
        if (kt + 1 < KT) {
            if (kt + 1 >= 2)
                mbar_wait(((kt + 1) & 1) ? mb1 : mb0, (((kt + 1) - 2) >> 1) & 1);
            fill_chunk(kt + 1);
            cp_wait<1>();
        } else {
            cp_wait<0>();
        }
        fence_async_smem();
        __syncthreads();
        if (wid == 0 && elect_one()) {
#pragma unroll
            for (int mb = 0; mb < 2; mb++) {
                uint64_t ad = desc_k(sbase + (buf * 2 + mb) * ABYTES);
#pragma unroll
                for (int r = 0; r < NRg; r++) {
                    uint64_t bd = desc_k(sbase + BOFF + (buf * NRg + r) * BBYTES);
#pragma unroll
                    for (int k4 = 0; k4 < 4; k4++)   // 16-k step: +2 desc units
                        tc_mma_f16_ss(tmem + mb * (MODE ? 128 : 256) + r * 64,
                                      ad + 2 * k4, bd + 2 * k4,
                                      MMA_IDESC, (kt > 0) || (k4 > 0));
                }
            }
            tc_commit(buf ? mb1 : mb0);
        }
    }
    mbar_wait(mb0, ((KT - 2) >> 1) & 1);
    mbar_wait(mb1, ((KT - 1) >> 1) & 1);
    tc_fence_after();

    // epilogue: 8 warps cover 256 rows; wid>>2 = m-block, wid&3 = subpartition
    {
        const int mb = wid >> 2;
        const int m  = rowbase + mb * 128 + (wid & 3) * 32 + lane;
        if (MODE == 0) {
            const int cb = mb * 256;
#pragma unroll
            for (int g4 = 0; g4 < 4; g4++) {         // 4 x 32 act cols
                uint32_t dp[32], dg[32];
                LDTM_X32(dp, tmem + cb + g4 * 32);
                LDTM_X32(dg, tmem + cb + 128 + g4 * 32);
                tc_wait_ld();
                if (m < rowlim) {
                    uint32_t hh[16];
#pragma unroll
                    for (int j = 0; j < 32; j += 2) {
                        float p0 = __uint_as_float(dp[j]), p1 = __uint_as_float(dp[j + 1]);
                        float g0 = __uint_as_float(dg[j]), g1 = __uint_as_float(dg[j + 1]);
                        float a0 = p0 * g0 / (1.0f + __expf(-p0));
                        float a1 = p1 * g1 / (1.0f + __expf(-p1));
                        __half2 h = __floats2half2_rn(a0, a1);
                        hh[j >> 1] = *(uint32_t*)&h;
                    }
                    uint4* dst = (uint4*)(g_Act + (size_t)m * INTERD + bn * 128 + g4 * 32);
#pragma unroll
                    for (int i = 0; i < 4; i++) dst[i] = ((uint4*)hh)[i];
                }
            }
        } else {
            const int cb = mb * 128;
            float* orow = g_Out2 + (size_t)m * HID + bn * 128;
#pragma unroll
            for (int g4 = 0; g4 < 4; g4++) {         // 4 x 32 out cols
                uint32_t d[32];
                LDTM_X32(d, tmem + cb + g4 * 32);
                tc_wait_ld();
                if (m < rowlim) {
                    uint4* dst = (uint4*)(orow + g4 * 32);
#pragma unroll
                    for (int i = 0; i < 8; i++) dst[i] = ((uint4*)d)[i];
                }
            }
        }
        tc_fence_before();
    }
    __syncthreads();
    if (wid == 0) tc_dealloc(tmem, TCOLS);

#else
    // ============ naive-correct fallback (insurance only) ============
    (void)smem; (void)wid; (void)lane;
    const int row = rowbase + tid;
    if (row >= rowlim) return;
    if (MODE == 0) {
        const __half* a = g_Xp + (size_t)row * HID;
        for (int j = 0; j < 128; j++) {
            const __half* wp = Wh + (size_t)(bn * 128 + j) * HID;
            const __half* wg = Wh + (size_t)(INTERD + bn * 128 + j) * HID;
            float p = 0.0f, g = 0.0f;
            for (int k = 0; k < HID; k++) {
                float av = __half2float(a[k]);
                p += av * __half2float(wp[k]);
                g += av * __half2float(wg[k]);
            }
            float act = p / (1.0f + __expf(-p)) * g;
            g_Act[(size_t)row * INTERD + bn * 128 + j] = __float2half_rn(act);
        }
    } else {
        const __half* a = g_Act + (size_t)row * INTERD;
        for (int j = 0; j < 128; j++) {
            const __half* wp = Wh + (size_t)(bn * 128 + j) * INTERD;
            float s = 0.0f;
            for (int k = 0; k < INTERD; k++)
                s += __half2float(a[k]) * __half2float(wp[k]);
            g_Out2[(size_t)row * HID + bn * 128 + j] = s;
        }
    }
#endif // USE_TC
}

// ---------------------------------------------------------------------------
extern "C" void kernel_launch(void* const* d_in, const int* in_sizes, int n_in,
                              void* d_out, int out_size) {
    const float* X      = (const float*)d_in[0];  // [2048,1024]
    const float* logits = (const float*)d_in[1];  // [2048,8]
    const float* w1     = (const float*)d_in[2];  // [8,1024,4096]
    const float* w2     = (const float*)d_in[3];  // [8,2048,1024]
    float* out          = (float*)d_out;          // [2048,1024]

    __half* w1h = nullptr; __half* w2h = nullptr;
    cudaGetSymbolAddress((void**)&w1h, g_W1h);
    cudaGetSymbolAddress((void**)&w2h, g_W2h);

    constexpr int SMEM1 = 4 * 16384 + 8 * 8192 + 32;  // 131104 (FC1)
    constexpr int SMEM2 = 4 * 16384 + 4 * 8192 + 32;  // 98336  (FC2)
    cudaFuncSetAttribute(moe_gemm_kernel<0>, cudaFuncAttributeMaxDynamicSharedMemorySize, SMEM1);
    cudaFuncSetAttribute(moe_gemm_kernel<1>, cudaFuncAttributeMaxDynamicSharedMemorySize, SMEM2);

    // 0: conv w1 (+ zero routing counters)
    convT_kernel<<<dim3(128, 32, NE), dim3(32, 8)>>>(w1, w1h, HID, 2 * INTERD, 1, 0, logits);
    // 1: conv w2 (+ top-2 routing in blocks x==0,y==0)
    convT_kernel<<<dim3(32, 64, NE), dim3(32, 8)>>>(w2, w2h, INTERD, HID, 0, 1, logits);
    // 2: scatter + permute (one block per pair)
    scatter_permute_kernel<<<NP, 128>>>(X);
    // 3: FC1 (+SwiGLU) — ncu-profiled slot
    moe_gemm_kernel<0><<<dim3(16, 16, NE), 256, SMEM1>>>();
    // 4: FC2 -> g_Out2
    moe_gemm_kernel<1><<<dim3(8, 16, NE), 256, SMEM2>>>();
    // 5: weighted combine (writes every output element)
    combine_kernel<<<NT, 256>>>(out);
}

// round 9
// speedup vs baseline: 1.1323x; 1.1323x over previous
#include <cuda_runtime.h>
#include <cuda_fp16.h>
#include <cstdint>

// ---------------------------------------------------------------------------
// MoE (AriaExperts): top-2 routing + grouped tcgen05 f16 GEMM (SwiGLU fused)
// tokens=2048, hidden=1024, inter=2048, experts=8, topk=2
//
// R9: occupancy-first. BM=256, BN=64 (FC1: TCOLS=256, SMEM 98KB; FC2:
// TCOLS=128, SMEM 82KB) -> 2 CTAs/SM by both smem and TMEM budgets.
// Keeps R8's compressed launch list (FC1 at profiled index 3), atomic-free
// FC2 (scratch + combine), fused routing/scatter. Validated MMA config
// (K-major SW128 SS, idesc 0x8100010) unchanged.
// ---------------------------------------------------------------------------

#if defined(__CUDA_ARCH__) && \
    (defined(__CUDA_ARCH_FEAT_SM103_ALL) || \
     (defined(__CUDA_ARCH_SPECIFIC__)) || \
     (defined(__CUDA_ARCH_FAMILY_SPECIFIC__)))
#define USE_TC 1
#else
#define USE_TC 0
#endif

#define NT     2048
#define HID    1024
#define INTERD 2048
#define NE     8
#define TK     2
#define NP     (NT*TK)
#define NPP    (NP + 256)    // BM=256 tile overrun padding

// ---- device scratch ----
__device__ __align__(16) __half g_Xp  [NPP * HID];
__device__ __align__(16) __half g_Act [NPP * INTERD];
__device__ __align__(16) float  g_Out2[NPP * HID];              // FC2 results per pair
__device__ __align__(16) __half g_W1h[NE * 2 * INTERD * HID];   // [E][4096][1024] k-contig
__device__ __align__(16) __half g_W2h[NE * HID * INTERD];       // [E][1024][2048] k-contig
__device__ int   g_counts[NE];
__device__ int   g_fill[NE];
__device__ int   g_offsets[NE + 1];
__device__ int   g_tok_e[NT * TK];
__device__ float g_tok_s[NT * TK];
__device__ int   g_tok_pos[NT * TK];

#define SW128(o) ((o) ^ (((o) >> 3) & 0x70))

// ---------------------------------------------------------------------------
// conv: weight transpose + fp32->fp16  (in [e][K][N] f32 -> out [e][N][K] f16)
// 32x32 tiles, block (32,8). zeroFlag: clear routing counters (conv1 only).
// routeFlag: blocks (x==0,y==0) additionally route 256 tokens each (conv2).
// ---------------------------------------------------------------------------
__global__ void convT_kernel(const float* __restrict__ in, __half* __restrict__ out,
                             int K, int N, int zeroFlag, int routeFlag,
                             const float* __restrict__ logits) {
    __shared__ float tile[32][33];
    const int e  = blockIdx.z;
    const int n0 = blockIdx.x * 32, k0 = blockIdx.y * 32;
    const float* ip = in  + (size_t)e * K * N;
    __half*      op = out + (size_t)e * N * K;
    const int tx = threadIdx.x, ty = threadIdx.y;
#pragma unroll
    for (int i = 0; i < 4; i++)
        tile[ty + i * 8][tx] = ip[(size_t)(k0 + ty + i * 8) * N + n0 + tx];
    __syncthreads();
#pragma unroll
    for (int i = 0; i < 4; i++)
        op[(size_t)(n0 + ty + i * 8) * K + k0 + tx] =
            __float2half_rn(tile[tx][ty + i * 8]);

    if (zeroFlag && blockIdx.x == 0 && blockIdx.y == 0 && blockIdx.z == 0 &&
        tx == 0 && ty == 0) {
#pragma unroll
        for (int i = 0; i < NE; i++) { g_counts[i] = 0; g_fill[i] = 0; }
    }
    if (routeFlag && blockIdx.x == 0 && blockIdx.y == 0) {
        // 8 z-blocks x 256 threads = 2048 tokens
        int t = blockIdx.z * 256 + ty * 32 + tx;
        float l[NE];
#pragma unroll
        for (int i = 0; i < NE; i++) l[i] = logits[t * NE + i];
        int b0 = 0; float v0 = l[0];
#pragma unroll
        for (int i = 1; i < NE; i++) if (l[i] > v0) { v0 = l[i]; b0 = i; }
        int b1 = -1; float v1 = -1e30f;
#pragma unroll
        for (int i = 0; i < NE; i++) if (i != b0 && l[i] > v1) { v1 = l[i]; b1 = i; }
        float e1  = __expf(v1 - v0);
        float inv = 1.0f / (1.0f + e1);
        g_tok_e[t * 2 + 0] = b0; g_tok_s[t * 2 + 0] = inv;
        g_tok_e[t * 2 + 1] = b1; g_tok_s[t * 2 + 1] = e1 * inv;
        atomicAdd(&g_counts[b0], 1);
        atomicAdd(&g_counts[b1], 1);
    }
}

// ---------------------------------------------------------------------------
// scatter + permute: one block per token-expert pair. Thread 0 claims the
// slot (local prefix over 8 counts + atomic fill), then 128 threads copy
// the token row (fp32->fp16) into the permuted buffer.
// ---------------------------------------------------------------------------
__global__ void scatter_permute_kernel(const float* __restrict__ X) {
    __shared__ int s_pos;
    const int p = blockIdx.x;          // pair id
    const int t = p >> 1;
    if (threadIdx.x == 0) {
        int e = g_tok_e[p];
        int s = 0, off = 0;
#pragma unroll
        for (int i = 0; i < NE; i++) { if (i == e) off = s; s += g_counts[i]; }
        int pos = off + atomicAdd(&g_fill[e], 1);
        g_tok_pos[p] = pos;
        s_pos = pos;
        if (p == 0) {
            int s2 = 0;
#pragma unroll
            for (int i = 0; i < NE; i++) { g_offsets[i] = s2; s2 += g_counts[i]; }
            g_offsets[NE] = s2;
        }
    }
    __syncthreads();
    const int pos = s_pos;
    const int c = threadIdx.x * 8;
    const float4* s = (const float4*)(X + (size_t)t * HID + c);
    float4 v0 = s[0], v1 = s[1];
    union { __half h[8]; uint4 u; } cv;
    cv.h[0] = __float2half_rn(v0.x); cv.h[1] = __float2half_rn(v0.y);
    cv.h[2] = __float2half_rn(v0.z); cv.h[3] = __float2half_rn(v0.w);
    cv.h[4] = __float2half_rn(v1.x); cv.h[5] = __float2half_rn(v1.y);
    cv.h[6] = __float2half_rn(v1.z); cv.h[7] = __float2half_rn(v1.w);
    *(uint4*)(g_Xp + (size_t)pos * HID + c) = cv.u;
}

// ---------------------------------------------------------------------------
// combine: out[t] = s0 * O2[pos0] + s1 * O2[pos1]   (writes every element)
// ---------------------------------------------------------------------------
__global__ void combine_kernel(float* __restrict__ out) {
    const int t = blockIdx.x;
    const int c = threadIdx.x * 4;
    const int   p0 = g_tok_pos[2 * t],     p1 = g_tok_pos[2 * t + 1];
    const float s0 = g_tok_s[2 * t],       s1 = g_tok_s[2 * t + 1];
    float4 a = *(const float4*)(g_Out2 + (size_t)p0 * HID + c);
    float4 b = *(const float4*)(g_Out2 + (size_t)p1 * HID + c);
    float4 r;
    r.x = s0 * a.x + s1 * b.x;  r.y = s0 * a.y + s1 * b.y;
    r.z = s0 * a.z + s1 * b.z;  r.w = s0 * a.w + s1 * b.w;
    *(float4*)(out + (size_t)t * HID + c) = r;
}

// ---------------------------------------------------------------------------
// tcgen05 helpers (arch-specific pass only)
// ---------------------------------------------------------------------------
#if USE_TC
__device__ __forceinline__ uint32_t elect_one() {
    uint32_t p;
    asm volatile("{\n\t.reg .pred p;\n\telect.sync _|p, 0xFFFFFFFF;\n\t"
                 "selp.b32 %0,1,0,p;\n\t}" : "=r"(p));
    return p;
}
__device__ __forceinline__ void mbar_init(uint32_t a, uint32_t c) {
    asm volatile("mbarrier.init.shared.b64 [%0], %1;" :: "r"(a), "r"(c) : "memory");
}
__device__ __forceinline__ void mbar_wait(uint32_t a, uint32_t par) {
    asm volatile("{\n\t.reg .pred P;\n\tWL_%=:\n\t"
                 "mbarrier.try_wait.parity.acquire.cta.shared::cta.b64 P, [%0], %1, 0x989680;\n\t"
                 "@P bra WD_%=;\n\tbra WL_%=;\n\tWD_%=:\n\t}"
                 :: "r"(a), "r"(par) : "memory");
}
__device__ __forceinline__ void tc_alloc(uint32_t slot, uint32_t n) {
    asm volatile("tcgen05.alloc.cta_group::1.sync.aligned.shared::cta.b32 [%0], %1;"
                 :: "r"(slot), "r"(n) : "memory");
}
__device__ __forceinline__ void tc_relinquish() {
    asm volatile("tcgen05.relinquish_alloc_permit.cta_group::1.sync.aligned;");
}
__device__ __forceinline__ void tc_dealloc(uint32_t t, uint32_t n) {
    asm volatile("tcgen05.dealloc.cta_group::1.sync.aligned.b32 %0, %1;" :: "r"(t), "r"(n));
}
__device__ __forceinline__ void tc_commit(uint32_t mbar) {
    asm volatile("tcgen05.commit.cta_group::1.mbarrier::arrive::one.shared::cluster.b64 [%0];"
                 :: "r"(mbar) : "memory");
}
__device__ __forceinline__ void tc_mma_f16_ss(uint32_t d, uint64_t ad, uint64_t bd,
                                              uint32_t idesc, uint32_t en) {
    asm volatile("{\n\t.reg .pred p;\n\tsetp.ne.u32 p, %4, 0;\n\t"
                 "tcgen05.mma.cta_group::1.kind::f16 [%0], %1, %2, %3, {%5,%5,%5,%5}, p;\n\t}"
                 :: "r"(d), "l"(ad), "l"(bd), "r"(idesc), "r"(en), "r"(0u) : "memory");
}
__device__ __forceinline__ void tc_fence_after()  { asm volatile("tcgen05.fence::after_thread_sync;"  ::: "memory"); }
__device__ __forceinline__ void tc_fence_before() { asm volatile("tcgen05.fence::before_thread_sync;" ::: "memory"); }
__device__ __forceinline__ void tc_wait_ld()      { asm volatile("tcgen05.wait::ld.sync.aligned;"     ::: "memory"); }
__device__ __forceinline__ void fence_async_smem(){ asm volatile("fence.proxy.async.shared::cta;"     ::: "memory"); }
__device__ __forceinline__ void cp16(uint32_t dst, const void* src) {
    asm volatile("cp.async.cg.shared.global [%0], [%1], 16;" :: "r"(dst), "l"(src));
}
__device__ __forceinline__ void cp_commit() { asm volatile("cp.async.commit_group;" ::: "memory"); }
template <int N> __device__ __forceinline__ void cp_wait() {
    asm volatile("cp.async.wait_group %0;" :: "n"(N) : "memory");
}

#define LDTM_X32(r, tmem_addr) \
    asm volatile( \
        "tcgen05.ld.sync.aligned.32x32b.x32.b32 " \
        "{%0, %1, %2, %3, %4, %5, %6, %7, " \
        " %8, %9, %10, %11, %12, %13, %14, %15, " \
        " %16, %17, %18, %19, %20, %21, %22, %23, " \
        " %24, %25, %26, %27, %28, %29, %30, %31}, [%32];" \
        : "=r"((r)[0]),  "=r"((r)[1]),  "=r"((r)[2]),  "=r"((r)[3]), \
          "=r"((r)[4]),  "=r"((r)[5]),  "=r"((r)[6]),  "=r"((r)[7]), \
          "=r"((r)[8]),  "=r"((r)[9]),  "=r"((r)[10]), "=r"((r)[11]), \
          "=r"((r)[12]), "=r"((r)[13]), "=r"((r)[14]), "=r"((r)[15]), \
          "=r"((r)[16]), "=r"((r)[17]), "=r"((r)[18]), "=r"((r)[19]), \
          "=r"((r)[20]), "=r"((r)[21]), "=r"((r)[22]), "=r"((r)[23]), \
          "=r"((r)[24]), "=r"((r)[25]), "=r"((r)[26]), "=r"((r)[27]), \
          "=r"((r)[28]), "=r"((r)[29]), "=r"((r)[30]), "=r"((r)[31]) \
        : "r"(tmem_addr))

// SMEM matrix descriptor: K-major SW128 (LBO=1, SBO=64, version=1, layout=2)
__device__ __forceinline__ uint64_t desc_k(uint32_t a) {
    return 0x4000404000010000ull | ((a >> 4) & 0x3FFF);
}
// idesc kind::f16: c=f32, a/b f16 K-major, N=64, M=128 (validated R6)
#define MMA_IDESC 0x8100010u
#endif // USE_TC

// ---------------------------------------------------------------------------
// Grouped GEMM.  256 threads, BM=256 (2 M=128 blocks), BN=64.
//   MODE 0 (FC1+SwiGLU): grid (32, 16, 8); 64 act cols; B = 2 regions (proj,gate)
//                        TMEM: mb*128 + r*64  (256 cols; 2 CTAs/SM fit TMEM)
//   MODE 1 (FC2):        grid (16, 16, 8); 64 out cols; B = 1 region
//                        TMEM: mb*64          (128 cols); writes g_Out2 fp32
// ---------------------------------------------------------------------------
template <int MODE>
__global__ __launch_bounds__(256)
void moe_gemm_kernel() {
    const int e   = blockIdx.z;
    const int cnt = g_counts[e];
    const int mt  = blockIdx.y;
    if (mt * 256 >= cnt) return;
    const int bn      = blockIdx.x;
    const int rowbase = g_offsets[e] + mt * 256;
    const int rowlim  = g_offsets[e] + cnt;

    constexpr int K = MODE ? INTERD : HID;
    const __half* __restrict__ Ag = MODE ? g_Act : g_Xp;
    const __half* __restrict__ Wh = MODE
        ? (g_W2h + (size_t)e * HID * INTERD)          // [1024][2048] k-contig
        : (g_W1h + (size_t)e * 2 * INTERD * HID);     // [4096][1024] k-contig

    extern __shared__ __align__(1024) char smem[];
    const int tid = threadIdx.x, wid = tid >> 5, lane = tid & 31;

#if USE_TC
    constexpr int KT     = K / 64;
    constexpr int NRg    = MODE ? 1 : 2;              // B regions of 64 n
    constexpr int TCOLS  = MODE ? 128 : 256;
    constexpr int ABYTES = 16384, BBYTES = 8192;
    constexpr int BOFF   = 4 * ABYTES;                // 2 bufs x 2 mblk
    constexpr int CTRL   = BOFF + 2 * NRg * BBYTES;

    uint32_t sbase = (uint32_t)__cvta_generic_to_shared(smem);
    uint32_t mb0 = sbase + CTRL + 8, mb1 = sbase + CTRL + 16;

    if (tid == 0) { mbar_init(mb0, 1); mbar_init(mb1, 1); }
    if (wid == 0) { tc_alloc(sbase + CTRL, TCOLS); tc_relinquish(); }
    __syncthreads();
    uint32_t tmem = *(volatile uint32_t*)(smem + CTRL);

    auto fill_chunk = [&](int j) {
        const int buf = j & 1;
        const int k0  = j * 64;
#pragma unroll
        for (int mb = 0; mb < 2; mb++) {
            uint32_t As = sbase + (buf * 2 + mb) * ABYTES;
            const __half* Ap = Ag + (size_t)(rowbase + mb * 128) * K + k0;
#pragma unroll
            for (int i = 0; i < 4; i++) {
                int u = i * 256 + tid, row = u >> 3, q = u & 7;
                cp16(As + SW128(row * 128 + q * 16), Ap + (size_t)row * K + q * 8);
            }
        }
#pragma unroll
        for (int r = 0; r < NRg; r++) {
            uint32_t Bs = sbase + BOFF + (buf * NRg + r) * BBYTES;
            const int nb = (MODE == 0 && r == 1) ? (INTERD + bn * 64) : (bn * 64);
            const __half* Bp = Wh + (size_t)nb * K + k0;
#pragma unroll
            for (int i = 0; i < 2; i++) {
                int u = i * 256 + tid, row = u >> 3, q = u & 7;
                cp16(Bs + SW128(row * 128 + q * 16), Bp + (size_t)row * K + q * 8);
            }
        }
        cp_commit();
    };

    fill_chunk(0);
    for (int kt = 0; kt < KT; kt++) {
        const int buf = kt & 1;
        if (kt + 1 < KT) {
            if (kt + 1 >= 2)
                mbar_wait(((kt + 1) & 1) ? mb1 : mb0, (((kt + 1) - 2) >> 1) & 1);
            fill_chunk(kt + 1);
            cp_wait<1>();
        } else {
            cp_wait<0>();
        }
        fence_async_smem();
        __syncthreads();
        if (wid == 0 && elect_one()) {
#pragma unroll
            for (int mb = 0; mb < 2; mb++) {
                uint64_t ad = desc_k(sbase + (buf * 2 + mb) * ABYTES);
#pragma unroll
                for (int r = 0; r < NRg; r++) {
                    uint64_t bd = desc_k(sbase + BOFF + (buf * NRg + r) * BBYTES);
#pragma unroll
                    for (int k4 = 0; k4 < 4; k4++)   // 16-k step: +2 desc units
                        tc_mma_f16_ss(tmem + mb * (NRg * 64) + r * 64,
                                      ad + 2 * k4, bd + 2 * k4,
                                      MMA_IDESC, (kt > 0) || (k4 > 0));
                }
            }
            tc_commit(buf ? mb1 : mb0);
        }
    }
    mbar_wait(mb0, ((KT - 2) >> 1) & 1);
    mbar_wait(mb1, ((KT - 1) >> 1) & 1);
    tc_fence_after();

    // epilogue: 8 warps cover 256 rows; wid>>2 = m-block, wid&3 = subpartition
    {
        const int mb = wid >> 2;
        const int m  = rowbase + mb * 128 + (wid & 3) * 32 + lane;
        if (MODE == 0) {
            const int cb = mb * 128;                 // proj at cb, gate at cb+64
#pragma unroll
            for (int pass = 0; pass < 2; pass++) {   // 2 x 32 act cols
                uint32_t dp[32], dg[32];
                LDTM_X32(dp, tmem + cb + pass * 32);
                LDTM_X32(dg, tmem + cb + 64 + pass * 32);
                tc_wait_ld();
                if (m < rowlim) {
                    uint32_t hh[16];
#pragma unroll
                    for (int j = 0; j < 32; j += 2) {
                        float p0 = __uint_as_float(dp[j]), p1 = __uint_as_float(dp[j + 1]);
                        float g0 = __uint_as_float(dg[j]), g1 = __uint_as_float(dg[j + 1]);
                        float a0 = p0 * g0 / (1.0f + __expf(-p0));
                        float a1 = p1 * g1 / (1.0f + __expf(-p1));
                        __half2 h = __floats2half2_rn(a0, a1);
                        hh[j >> 1] = *(uint32_t*)&h;
                    }
                    uint4* dst = (uint4*)(g_Act + (size_t)m * INTERD + bn * 64 + pass * 32);
#pragma unroll
                    for (int i = 0; i < 4; i++) dst[i] = ((uint4*)hh)[i];
                }
            }
        } else {
            const int cb = mb * 64;
            float* orow = g_Out2 + (size_t)m * HID + bn * 64;
#pragma unroll
            for (int pass = 0; pass < 2; pass++) {   // 2 x 32 out cols
                uint32_t d[32];
                LDTM_X32(d, tmem + cb + pass * 32);
                tc_wait_ld();
                if (m < rowlim) {
                    uint4* dst = (uint4*)(orow + pass * 32);
#pragma unroll
                    for (int i = 0; i < 8; i++) dst[i] = ((uint4*)d)[i];
                }
            }
        }
        tc_fence_before();
    }
    __syncthreads();
    if (wid == 0) tc_dealloc(tmem, TCOLS);

#else
    // ============ naive-correct fallback (insurance only) ============
    (void)smem; (void)wid; (void)lane;
    const int row = rowbase + tid;
    if (row >= rowlim) return;
    if (MODE == 0) {
        const __half* a = g_Xp + (size_t)row * HID;
        for (int j = 0; j < 64; j++) {
            const __half* wp = Wh + (size_t)(bn * 64 + j) * HID;
            const __half* wg = Wh + (size_t)(INTERD + bn * 64 + j) * HID;
            float p = 0.0f, g = 0.0f;
            for (int k = 0; k < HID; k++) {
                float av = __half2float(a[k]);
                p += av * __half2float(wp[k]);
                g += av * __half2float(wg[k]);
            }
            float act = p / (1.0f + __expf(-p)) * g;
            g_Act[(size_t)row * INTERD + bn * 64 + j] = __float2half_rn(act);
        }
    } else {
        const __half* a = g_Act + (size_t)row * INTERD;
        for (int j = 0; j < 64; j++) {
            const __half* wp = Wh + (size_t)(bn * 64 + j) * INTERD;
            float s = 0.0f;
            for (int k = 0; k < INTERD; k++)
                s += __half2float(a[k]) * __half2float(wp[k]);
            g_Out2[(size_t)row * HID + bn * 64 + j] = s;
        }
    }
#endif // USE_TC
}

// ---------------------------------------------------------------------------
extern "C" void kernel_launch(void* const* d_in, const int* in_sizes, int n_in,
                              void* d_out, int out_size) {
    const float* X      = (const float*)d_in[0];  // [2048,1024]
    const float* logits = (const float*)d_in[1];  // [2048,8]
    const float* w1     = (const float*)d_in[2];  // [8,1024,4096]
    const float* w2     = (const float*)d_in[3];  // [8,2048,1024]
    float* out          = (float*)d_out;          // [2048,1024]

    __half* w1h = nullptr; __half* w2h = nullptr;
    cudaGetSymbolAddress((void**)&w1h, g_W1h);
    cudaGetSymbolAddress((void**)&w2h, g_W2h);

    constexpr int SMEM1 = 4 * 16384 + 4 * 8192 + 32;  // 98336 (FC1) -> 2 CTAs/SM
    constexpr int SMEM2 = 4 * 16384 + 2 * 8192 + 32;  // 81952 (FC2) -> 2 CTAs/SM
    cudaFuncSetAttribute(moe_gemm_kernel<0>, cudaFuncAttributeMaxDynamicSharedMemorySize, SMEM1);
    cudaFuncSetAttribute(moe_gemm_kernel<1>, cudaFuncAttributeMaxDynamicSharedMemorySize, SMEM2);

    // 0: conv w1 (+ zero routing counters)
    convT_kernel<<<dim3(128, 32, NE), dim3(32, 8)>>>(w1, w1h, HID, 2 * INTERD, 1, 0, logits);
    // 1: conv w2 (+ top-2 routing in blocks x==0,y==0)
    convT_kernel<<<dim3(32, 64, NE), dim3(32, 8)>>>(w2, w2h, INTERD, HID, 0, 1, logits);
    // 2: scatter + permute (one block per pair)
    scatter_permute_kernel<<<NP, 128>>>(X);
    // 3: FC1 (+SwiGLU) — ncu-profiled slot
    moe_gemm_kernel<0><<<dim3(32, 16, NE), 256, SMEM1>>>();
    // 4: FC2 -> g_Out2
    moe_gemm_kernel<1><<<dim3(16, 16, NE), 256, SMEM2>>>();
    // 5: weighted combine (writes every output element)
    combine_kernel<<<NT, 256>>>(out);
}

// round 10
// speedup vs baseline: 1.2074x; 1.0662x over previous
#include <cuda_runtime.h>
#include <cuda_fp16.h>
#include <cstdint>

// ---------------------------------------------------------------------------
// MoE (AriaExperts): top-2 routing + grouped tcgen05 f16 GEMM (SwiGLU fused)
// tokens=2048, hidden=1024, inter=2048, experts=8, topk=2
//
// R10: latency-focused GEMM. BM=128, single N=128 MMA per 64-k chunk
// (FC1: B = [proj64|gate64] rows), 3-stage smem pipeline, issue-first loop
// (MMA issued before buffer-reuse wait + next fill). 2 CTAs/SM (96KB smem,
// 128 TMEM cols). Validated K-major SW128 SS desc config unchanged.
// ---------------------------------------------------------------------------

#if defined(__CUDA_ARCH__) && \
    (defined(__CUDA_ARCH_FEAT_SM103_ALL) || \
     (defined(__CUDA_ARCH_SPECIFIC__)) || \
     (defined(__CUDA_ARCH_FAMILY_SPECIFIC__)))
#define USE_TC 1
#else
#define USE_TC 0
#endif

#define NT     2048
#define HID    1024
#define INTERD 2048
#define NE     8
#define TK     2
#define NP     (NT*TK)
#define NPP    (NP + 256)

// ---- device scratch ----
__device__ __align__(16) __half g_Xp  [NPP * HID];
__device__ __align__(16) __half g_Act [NPP * INTERD];
__device__ __align__(16) float  g_Out2[NPP * HID];              // FC2 results per pair
__device__ __align__(16) __half g_W1h[NE * 2 * INTERD * HID];   // [E][4096][1024] k-contig
__device__ __align__(16) __half g_W2h[NE * HID * INTERD];       // [E][1024][2048] k-contig
__device__ int   g_counts[NE];
__device__ int   g_fill[NE];
__device__ int   g_offsets[NE + 1];
__device__ int   g_tok_e[NT * TK];
__device__ float g_tok_s[NT * TK];
__device__ int   g_tok_pos[NT * TK];

#define SW128(o) ((o) ^ (((o) >> 3) & 0x70))

// ---------------------------------------------------------------------------
// conv: weight transpose + fp32->fp16  (in [e][K][N] f32 -> out [e][N][K] f16)
// ---------------------------------------------------------------------------
__global__ void convT_kernel(const float* __restrict__ in, __half* __restrict__ out,
                             int K, int N, int zeroFlag, int routeFlag,
                             const float* __restrict__ logits) {
    __shared__ float tile[32][33];
    const int e  = blockIdx.z;
    const int n0 = blockIdx.x * 32, k0 = blockIdx.y * 32;
    const float* ip = in  + (size_t)e * K * N;
    __half*      op = out + (size_t)e * N * K;
    const int tx = threadIdx.x, ty = threadIdx.y;
#pragma unroll
    for (int i = 0; i < 4; i++)
        tile[ty + i * 8][tx] = ip[(size_t)(k0 + ty + i * 8) * N + n0 + tx];
    __syncthreads();
#pragma unroll
    for (int i = 0; i < 4; i++)
        op[(size_t)(n0 + ty + i * 8) * K + k0 + tx] =
            __float2half_rn(tile[tx][ty + i * 8]);

    if (zeroFlag && blockIdx.x == 0 && blockIdx.y == 0 && blockIdx.z == 0 &&
        tx == 0 && ty == 0) {
#pragma unroll
        for (int i = 0; i < NE; i++) { g_counts[i] = 0; g_fill[i] = 0; }
    }
    if (routeFlag && blockIdx.x == 0 && blockIdx.y == 0) {
        int t = blockIdx.z * 256 + ty * 32 + tx;
        float l[NE];
#pragma unroll
        for (int i = 0; i < NE; i++) l[i] = logits[t * NE + i];
        int b0 = 0; float v0 = l[0];
#pragma unroll
        for (int i = 1; i < NE; i++) if (l[i] > v0) { v0 = l[i]; b0 = i; }
        int b1 = -1; float v1 = -1e30f;
#pragma unroll
        for (int i = 0; i < NE; i++) if (i != b0 && l[i] > v1) { v1 = l[i]; b1 = i; }
        float e1  = __expf(v1 - v0);
        float inv = 1.0f / (1.0f + e1);
        g_tok_e[t * 2 + 0] = b0; g_tok_s[t * 2 + 0] = inv;
        g_tok_e[t * 2 + 1] = b1; g_tok_s[t * 2 + 1] = e1 * inv;
        atomicAdd(&g_counts[b0], 1);
        atomicAdd(&g_counts[b1], 1);
    }
}

// ---------------------------------------------------------------------------
// scatter + permute: one block per token-expert pair.
// ---------------------------------------------------------------------------
__global__ void scatter_permute_kernel(const float* __restrict__ X) {
    __shared__ int s_pos;
    const int p = blockIdx.x;
    const int t = p >> 1;
    if (threadIdx.x == 0) {
        int e = g_tok_e[p];
        int s = 0, off = 0;
#pragma unroll
        for (int i = 0; i < NE; i++) { if (i == e) off = s; s += g_counts[i]; }
        int pos = off + atomicAdd(&g_fill[e], 1);
        g_tok_pos[p] = pos;
        s_pos = pos;
        if (p == 0) {
            int s2 = 0;
#pragma unroll
            for (int i = 0; i < NE; i++) { g_offsets[i] = s2; s2 += g_counts[i]; }
            g_offsets[NE] = s2;
        }
    }
    __syncthreads();
    const int pos = s_pos;
    const int c = threadIdx.x * 8;
    const float4* s = (const float4*)(X + (size_t)t * HID + c);
    float4 v0 = s[0], v1 = s[1];
    union { __half h[8]; uint4 u; } cv;
    cv.h[0] = __float2half_rn(v0.x); cv.h[1] = __float2half_rn(v0.y);
    cv.h[2] = __float2half_rn(v0.z); cv.h[3] = __float2half_rn(v0.w);
    cv.h[4] = __float2half_rn(v1.x); cv.h[5] = __float2half_rn(v1.y);
    cv.h[6] = __float2half_rn(v1.z); cv.h[7] = __float2half_rn(v1.w);
    *(uint4*)(g_Xp + (size_t)pos * HID + c) = cv.u;
}

// ---------------------------------------------------------------------------
// combine: out[t] = s0 * O2[pos0] + s1 * O2[pos1]
// ---------------------------------------------------------------------------
__global__ void combine_kernel(float* __restrict__ out) {
    const int t = blockIdx.x;
    const int c = threadIdx.x * 4;
    const int   p0 = g_tok_pos[2 * t],     p1 = g_tok_pos[2 * t + 1];
    const float s0 = g_tok_s[2 * t],       s1 = g_tok_s[2 * t + 1];
    float4 a = *(const float4*)(g_Out2 + (size_t)p0 * HID + c);
    float4 b = *(const float4*)(g_Out2 + (size_t)p1 * HID + c);
    float4 r;
    r.x = s0 * a.x + s1 * b.x;  r.y = s0 * a.y + s1 * b.y;
    r.z = s0 * a.z + s1 * b.z;  r.w = s0 * a.w + s1 * b.w;
    *(float4*)(out + (size_t)t * HID + c) = r;
}

// ---------------------------------------------------------------------------
// tcgen05 helpers (arch-specific pass only)
// ---------------------------------------------------------------------------
#if USE_TC
__device__ __forceinline__ uint32_t elect_one() {
    uint32_t p;
    asm volatile("{\n\t.reg .pred p;\n\telect.sync _|p, 0xFFFFFFFF;\n\t"
                 "selp.b32 %0,1,0,p;\n\t}" : "=r"(p));
    return p;
}
__device__ __forceinline__ void mbar_init(uint32_t a, uint32_t c) {
    asm volatile("mbarrier.init.shared.b64 [%0], %1;" :: "r"(a), "r"(c) : "memory");
}
__device__ __forceinline__ void mbar_wait(uint32_t a, uint32_t par) {
    asm volatile("{\n\t.reg .pred P;\n\tWL_%=:\n\t"
                 "mbarrier.try_wait.parity.acquire.cta.shared::cta.b64 P, [%0], %1, 0x989680;\n\t"
                 "@P bra WD_%=;\n\tbra WL_%=;\n\tWD_%=:\n\t}"
                 :: "r"(a), "r"(par) : "memory");
}
__device__ __forceinline__ void tc_alloc(uint32_t slot, uint32_t n) {
    asm volatile("tcgen05.alloc.cta_group::1.sync.aligned.shared::cta.b32 [%0], %1;"
                 :: "r"(slot), "r"(n) : "memory");
}
__device__ __forceinline__ void tc_relinquish() {
    asm volatile("tcgen05.relinquish_alloc_permit.cta_group::1.sync.aligned;");
}
__device__ __forceinline__ void tc_dealloc(uint32_t t, uint32_t n) {
    asm volatile("tcgen05.dealloc.cta_group::1.sync.aligned.b32 %0, %1;" :: "r"(t), "r"(n));
}
__device__ __forceinline__ void tc_commit(uint32_t mbar) {
    asm volatile("tcgen05.commit.cta_group::1.mbarrier::arrive::one.shared::cluster.b64 [%0];"
                 :: "r"(mbar) : "memory");
}
__device__ __forceinline__ void tc_mma_f16_ss(uint32_t d, uint64_t ad, uint64_t bd,
                                              uint32_t idesc, uint32_t en) {
    asm volatile("{\n\t.reg .pred p;\n\tsetp.ne.u32 p, %4, 0;\n\t"
                 "tcgen05.mma.cta_group::1.kind::f16 [%0], %1, %2, %3, {%5,%5,%5,%5}, p;\n\t}"
                 :: "r"(d), "l"(ad), "l"(bd), "r"(idesc), "r"(en), "r"(0u) : "memory");
}
__device__ __forceinline__ void tc_fence_after()  { asm volatile("tcgen05.fence::after_thread_sync;"  ::: "memory"); }
__device__ __forceinline__ void tc_fence_before() { asm volatile("tcgen05.fence::before_thread_sync;" ::: "memory"); }
__device__ __forceinline__ void tc_wait_ld()      { asm volatile("tcgen05.wait::ld.sync.aligned;"     ::: "memory"); }
__device__ __forceinline__ void fence_async_smem(){ asm volatile("fence.proxy.async.shared::cta;"     ::: "memory"); }
__device__ __forceinline__ void cp16(uint32_t dst, const void* src) {
    asm volatile("cp.async.cg.shared.global [%0], [%1], 16;" :: "r"(dst), "l"(src));
}
__device__ __forceinline__ void cp_commit() { asm volatile("cp.async.commit_group;" ::: "memory"); }
template <int N> __device__ __forceinline__ void cp_wait() {
    asm volatile("cp.async.wait_group %0;" :: "n"(N) : "memory");
}

#define LDTM_X32(r, tmem_addr) \
    asm volatile( \
        "tcgen05.ld.sync.aligned.32x32b.x32.b32 " \
        "{%0, %1, %2, %3, %4, %5, %6, %7, " \
        " %8, %9, %10, %11, %12, %13, %14, %15, " \
        " %16, %17, %18, %19, %20, %21, %22, %23, " \
        " %24, %25, %26, %27, %28, %29, %30, %31}, [%32];" \
        : "=r"((r)[0]),  "=r"((r)[1]),  "=r"((r)[2]),  "=r"((r)[3]), \
          "=r"((r)[4]),  "=r"((r)[5]),  "=r"((r)[6]),  "=r"((r)[7]), \
          "=r"((r)[8]),  "=r"((r)[9]),  "=r"((r)[10]), "=r"((r)[11]), \
          "=r"((r)[12]), "=r"((r)[13]), "=r"((r)[14]), "=r"((r)[15]), \
          "=r"((r)[16]), "=r"((r)[17]), "=r"((r)[18]), "=r"((r)[19]), \
          "=r"((r)[20]), "=r"((r)[21]), "=r"((r)[22]), "=r"((r)[23]), \
          "=r"((r)[24]), "=r"((r)[25]), "=r"((r)[26]), "=r"((r)[27]), \
          "=r"((r)[28]), "=r"((r)[29]), "=r"((r)[30]), "=r"((r)[31]) \
        : "r"(tmem_addr))

// SMEM matrix descriptor: K-major SW128 (LBO=1, SBO=64, version=1, layout=2)
__device__ __forceinline__ uint64_t desc_k(uint32_t a) {
    return 0x4000404000010000ull | ((a >> 4) & 0x3FFF);
}
// idesc kind::f16: c=f32, a/b f16 K-major, M=128; N=128 -> (16<<17)
#define MMA_IDESC_N128 0x8200010u
#endif // USE_TC

// ---------------------------------------------------------------------------
// Grouped GEMM.  256 threads, BM=128, one N=128 MMA per 64-k chunk.
//   MODE 0 (FC1+SwiGLU): grid (32, 32, 8); 64 act cols (proj+gate packed)
//   MODE 1 (FC2):        grid (8, 32, 8);  128 out cols -> g_Out2 fp32
// 3 smem stages (32KB each: A 16KB + B 16KB), issue-first loop.
// ---------------------------------------------------------------------------
template <int MODE>
__global__ __launch_bounds__(256)
void moe_gemm_kernel() {
    const int e   = blockIdx.z;
    const int cnt = g_counts[e];
    const int mt  = blockIdx.y;
    if (mt * 128 >= cnt) return;
    const int bn      = blockIdx.x;
    const int rowbase = g_offsets[e] + mt * 128;
    const int rowlim  = g_offsets[e] + cnt;

    constexpr int K = MODE ? INTERD : HID;
    const __half* __restrict__ Ag = MODE ? g_Act : g_Xp;
    const __half* __restrict__ Wh = MODE
        ? (g_W2h + (size_t)e * HID * INTERD)          // [1024][2048] k-contig
        : (g_W1h + (size_t)e * 2 * INTERD * HID);     // [4096][1024] k-contig

    extern __shared__ __align__(1024) char smem[];
    const int tid = threadIdx.x, wid = tid >> 5, lane = tid & 31;

#if USE_TC
    constexpr int KT    = K / 64;
    constexpr int ST    = 3;                          // pipeline stages
    constexpr int STAGE = 32768;                      // A 16KB + B 16KB
    constexpr int CTRL  = ST * STAGE;

    uint32_t sbase = (uint32_t)__cvta_generic_to_shared(smem);
    uint32_t bar[ST];
#pragma unroll
    for (int b = 0; b < ST; b++) bar[b] = sbase + CTRL + 8 + b * 8;

    if (tid == 0) {
#pragma unroll
        for (int b = 0; b < ST; b++) mbar_init(bar[b], 1);
    }
    if (wid == 0) { tc_alloc(sbase + CTRL, 128); tc_relinquish(); }
    __syncthreads();
    uint32_t tmem = *(volatile uint32_t*)(smem + CTRL);

    // fill chunk j into stage j%ST: A 128rows x 64k (16KB), B 128rows x 64k (16KB)
    auto fill_chunk = [&](int j) {
        const uint32_t stg = sbase + (j % ST) * STAGE;
        const int k0 = j * 64;
        const __half* Ap = Ag + (size_t)rowbase * K + k0;
#pragma unroll
        for (int i = 0; i < 4; i++) {
            int u = i * 256 + tid, row = u >> 3, q = u & 7;
            cp16(stg + SW128(row * 128 + q * 16), Ap + (size_t)row * K + q * 8);
        }
#pragma unroll
        for (int i = 0; i < 4; i++) {
            int u = i * 256 + tid, row = u >> 3, q = u & 7;
            size_t ncol = (MODE == 0)
                ? (size_t)(bn * 64 + row + (row >= 64 ? (INTERD - 64) : 0))
                : (size_t)(bn * 128 + row);
            cp16(stg + 16384 + SW128(row * 128 + q * 16), Wh + ncol * K + k0 + q * 8);
        }
        cp_commit();
    };

    // prologue: data(0) ready, fill(1) in flight
    fill_chunk(0);
    if (KT > 1) fill_chunk(1);
    cp_wait<1>();
    fence_async_smem();
    __syncthreads();

    for (int kt = 0; kt < KT; kt++) {
        // 1) issue MMA for chunk kt immediately (data ready from prior iter)
        if (wid == 0 && elect_one()) {
            const uint32_t stg = sbase + (kt % ST) * STAGE;
            uint64_t ad = desc_k(stg);
            uint64_t bd = desc_k(stg + 16384);
#pragma unroll
            for (int k4 = 0; k4 < 4; k4++)
                tc_mma_f16_ss(tmem, ad + 2 * k4, bd + 2 * k4,
                              MMA_IDESC_N128, (kt > 0) || (k4 > 0));
            tc_commit(bar[kt % ST]);
        }
        // 2) prefill chunk kt+2 (buffer reuse gated on commit(kt-1))
        const int j = kt + 2;
        if (j < KT) {
            if (j >= ST) mbar_wait(bar[j % ST], ((j / ST) - 1) & 1);
            fill_chunk(j);
            cp_wait<1>();            // data(kt+1) complete
            fence_async_smem();
            __syncthreads();
        } else if (kt + 1 < KT) {
            cp_wait<0>();            // data(kt+1) complete
            fence_async_smem();
            __syncthreads();
        }
    }
    // wait last commit on each barrier
#pragma unroll
    for (int b = 0; b < ST; b++) {
        int ktm = KT - 1 - ((KT - 1 - b) % ST);
        mbar_wait(bar[b], (ktm / ST) & 1);
    }
    tc_fence_after();

    // epilogue: 8 warps; subpartition = wid&3, column-pass = wid>>2
    {
        const int sp = wid & 3, hp = wid >> 2;
        const int m  = rowbase + sp * 32 + lane;
        if (MODE == 0) {
            // pass hp covers act cols hp*32..hp*32+31 (proj cols = TMEM 0-63, gate 64-127)
            uint32_t dp[32], dg[32];
            LDTM_X32(dp, tmem + hp * 32);
            LDTM_X32(dg, tmem + 64 + hp * 32);
            tc_wait_ld();
            if (m < rowlim) {
                uint32_t hh[16];
#pragma unroll
                for (int j = 0; j < 32; j += 2) {
                    float p0 = __uint_as_float(dp[j]), p1 = __uint_as_float(dp[j + 1]);
                    float g0 = __uint_as_float(dg[j]), g1 = __uint_as_float(dg[j + 1]);
                    float a0 = p0 * g0 / (1.0f + __expf(-p0));
                    float a1 = p1 * g1 / (1.0f + __expf(-p1));
                    __half2 h = __floats2half2_rn(a0, a1);
                    hh[j >> 1] = *(uint32_t*)&h;
                }
                uint4* dst = (uint4*)(g_Act + (size_t)m * INTERD + bn * 64 + hp * 32);
#pragma unroll
                for (int i = 0; i < 4; i++) dst[i] = ((uint4*)hh)[i];
            }
        } else {
            // pass hp covers out cols hp*64..hp*64+63
            float* orow = g_Out2 + (size_t)m * HID + bn * 128 + hp * 64;
#pragma unroll
            for (int half = 0; half < 2; half++) {
                uint32_t d[32];
                LDTM_X32(d, tmem + hp * 64 + half * 32);
                tc_wait_ld();
                if (m < rowlim) {
                    uint4* dst = (uint4*)(orow + half * 32);
#pragma unroll
                    for (int i = 0; i < 8; i++) dst[i] = ((uint4*)d)[i];
                }
            }
        }
        tc_fence_before();
    }
    __syncthreads();
    if (wid == 0) tc_dealloc(tmem, 128);

#else
    // ============ naive-correct fallback (insurance only) ============
    (void)smem; (void)wid; (void)lane;
    if (tid >= 128) return;
    const int row = rowbase + tid;
    if (row >= rowlim) return;
    if (MODE == 0) {
        const __half* a = g_Xp + (size_t)row * HID;
        for (int j = 0; j < 64; j++) {
            const __half* wp = Wh + (size_t)(bn * 64 + j) * HID;
            const __half* wg = Wh + (size_t)(INTERD + bn * 64 + j) * HID;
            float p = 0.0f, g = 0.0f;
            for (int k = 0; k < HID; k++) {
                float av = __half2float(a[k]);
                p += av * __half2float(wp[k]);
                g += av * __half2float(wg[k]);
            }
            float act = p / (1.0f + __expf(-p)) * g;
            g_Act[(size_t)row * INTERD + bn * 64 + j] = __float2half_rn(act);
        }
    } else {
        const __half* a = g_Act + (size_t)row * INTERD;
        for (int j = 0; j < 128; j++) {
            const __half* wp = Wh + (size_t)(bn * 128 + j) * INTERD;
            float s = 0.0f;
            for (int k = 0; k < INTERD; k++)
                s += __half2float(a[k]) * __half2float(wp[k]);
            g_Out2[(size_t)row * HID + bn * 128 + j] = s;
        }
    }
#endif // USE_TC
}

// ---------------------------------------------------------------------------
extern "C" void kernel_launch(void* const* d_in, const int* in_sizes, int n_in,
                              void* d_out, int out_size) {
    const float* X      = (const float*)d_in[0];  // [2048,1024]
    const float* logits = (const float*)d_in[1];  // [2048,8]
    const float* w1     = (const float*)d_in[2];  // [8,1024,4096]
    const float* w2     = (const float*)d_in[3];  // [8,2048,1024]
    float* out          = (float*)d_out;          // [2048,1024]

    __half* w1h = nullptr; __half* w2h = nullptr;
    cudaGetSymbolAddress((void**)&w1h, g_W1h);
    cudaGetSymbolAddress((void**)&w2h, g_W2h);

    constexpr int SMEM = 3 * 32768 + 8 + 3 * 8;   // 98336 -> 2 CTAs/SM
    cudaFuncSetAttribute(moe_gemm_kernel<0>, cudaFuncAttributeMaxDynamicSharedMemorySize, SMEM);
    cudaFuncSetAttribute(moe_gemm_kernel<1>, cudaFuncAttributeMaxDynamicSharedMemorySize, SMEM);

    // 0: conv w1 (+ zero routing counters)
    convT_kernel<<<dim3(128, 32, NE), dim3(32, 8)>>>(w1, w1h, HID, 2 * INTERD, 1, 0, logits);
    // 1: conv w2 (+ top-2 routing in blocks x==0,y==0)
    convT_kernel<<<dim3(32, 64, NE), dim3(32, 8)>>>(w2, w2h, INTERD, HID, 0, 1, logits);
    // 2: scatter + permute (one block per pair)
    scatter_permute_kernel<<<NP, 128>>>(X);
    // 3: FC1 (+SwiGLU) — ncu-profiled slot
    moe_gemm_kernel<0><<<dim3(32, 32, NE), 256, SMEM>>>();
    // 4: FC2 -> g_Out2
    moe_gemm_kernel<1><<<dim3(8, 32, NE), 256, SMEM>>>();
    // 5: weighted combine
    combine_kernel<<<NT, 256>>>(out);
}

// round 11
// speedup vs baseline: 1.2632x; 1.0463x over previous
#include <cuda_runtime.h>
#include <cuda_fp16.h>
#include <cuda.h>
#include <cstdint>

// ---------------------------------------------------------------------------
// MoE (AriaExperts): top-2 routing + grouped tcgen05 f16 GEMM (SwiGLU fused)
// tokens=2048, hidden=1024, inter=2048, experts=8, topk=2
//
// R11: TMA-fed GEMM. Fills are UTMALDG (one instruction per tile, swizzle in
// HW, mbarrier expect_tx completion) instead of 2048 cp.async per chunk.
// Thread 0 drives the whole pipeline (TMA issue + MMA issue + commits);
// no per-chunk __syncthreads. 3 stages, 2 CTAs/SM. Validated K-major SW128
// SS MMA config (idesc N=128: 0x8200010) unchanged.
// ---------------------------------------------------------------------------

#if defined(__CUDA_ARCH__) && \
    (defined(__CUDA_ARCH_FEAT_SM103_ALL) || \
     (defined(__CUDA_ARCH_SPECIFIC__)) || \
     (defined(__CUDA_ARCH_FAMILY_SPECIFIC__)))
#define USE_TC 1
#else
#define USE_TC 0
#endif

#define NT     2048
#define HID    1024
#define INTERD 2048
#define NE     8
#define TK     2
#define NP     (NT*TK)
#define NPP    (NP + 256)

// ---- device scratch ----
__device__ __align__(16) __half g_Xp  [NPP * HID];
__device__ __align__(16) __half g_Act [NPP * INTERD];
__device__ __align__(16) float  g_Out2[NPP * HID];
__device__ __align__(16) __half g_W1h[NE * 2 * INTERD * HID];   // [E][4096][1024] k-contig
__device__ __align__(16) __half g_W2h[NE * HID * INTERD];       // [E][1024][2048] k-contig
__device__ int   g_counts[NE];
__device__ int   g_fill[NE];
__device__ int   g_offsets[NE + 1];
__device__ int   g_tok_e[NT * TK];
__device__ float g_tok_s[NT * TK];
__device__ int   g_tok_pos[NT * TK];

#define SW128(o) ((o) ^ (((o) >> 3) & 0x70))

// ---------------------------------------------------------------------------
// conv: weight transpose + fp32->fp16  (in [e][K][N] f32 -> out [e][N][K] f16)
// ---------------------------------------------------------------------------
__global__ void convT_kernel(const float* __restrict__ in, __half* __restrict__ out,
                             int K, int N, int zeroFlag, int routeFlag,
                             const float* __restrict__ logits) {
    __shared__ float tile[32][33];
    const int e  = blockIdx.z;
    const int n0 = blockIdx.x * 32, k0 = blockIdx.y * 32;
    const float* ip = in  + (size_t)e * K * N;
    __half*      op = out + (size_t)e * N * K;
    const int tx = threadIdx.x, ty = threadIdx.y;
#pragma unroll
    for (int i = 0; i < 4; i++)
        tile[ty + i * 8][tx] = ip[(size_t)(k0 + ty + i * 8) * N + n0 + tx];
    __syncthreads();
#pragma unroll
    for (int i = 0; i < 4; i++)
        op[(size_t)(n0 + ty + i * 8) * K + k0 + tx] =
            __float2half_rn(tile[tx][ty + i * 8]);

    if (zeroFlag && blockIdx.x == 0 && blockIdx.y == 0 && blockIdx.z == 0 &&
        tx == 0 && ty == 0) {
#pragma unroll
        for (int i = 0; i < NE; i++) { g_counts[i] = 0; g_fill[i] = 0; }
    }
    if (routeFlag && blockIdx.x == 0 && blockIdx.y == 0) {
        int t = blockIdx.z * 256 + ty * 32 + tx;
        float l[NE];
#pragma unroll
        for (int i = 0; i < NE; i++) l[i] = logits[t * NE + i];
        int b0 = 0; float v0 = l[0];
#pragma unroll
        for (int i = 1; i < NE; i++) if (l[i] > v0) { v0 = l[i]; b0 = i; }
        int b1 = -1; float v1 = -1e30f;
#pragma unroll
        for (int i = 0; i < NE; i++) if (i != b0 && l[i] > v1) { v1 = l[i]; b1 = i; }
        float e1  = __expf(v1 - v0);
        float inv = 1.0f / (1.0f + e1);
        g_tok_e[t * 2 + 0] = b0; g_tok_s[t * 2 + 0] = inv;
        g_tok_e[t * 2 + 1] = b1; g_tok_s[t * 2 + 1] = e1 * inv;
        atomicAdd(&g_counts[b0], 1);
        atomicAdd(&g_counts[b1], 1);
    }
}

// ---------------------------------------------------------------------------
// scatter + permute: one block per token-expert pair.
// ---------------------------------------------------------------------------
__global__ void scatter_permute_kernel(const float* __restrict__ X) {
    __shared__ int s_pos;
    const int p = blockIdx.x;
    const int t = p >> 1;
    if (threadIdx.x == 0) {
        int e = g_tok_e[p];
        int s = 0, off = 0;
#pragma unroll
        for (int i = 0; i < NE; i++) { if (i == e) off = s; s += g_counts[i]; }
        int pos = off + atomicAdd(&g_fill[e], 1);
        g_tok_pos[p] = pos;
        s_pos = pos;
        if (p == 0) {
            int s2 = 0;
#pragma unroll
            for (int i = 0; i < NE; i++) { g_offsets[i] = s2; s2 += g_counts[i]; }
            g_offsets[NE] = s2;
        }
    }
    __syncthreads();
    const int pos = s_pos;
    const int c = threadIdx.x * 8;
    const float4* s = (const float4*)(X + (size_t)t * HID + c);
    float4 v0 = s[0], v1 = s[1];
    union { __half h[8]; uint4 u; } cv;
    cv.h[0] = __float2half_rn(v0.x); cv.h[1] = __float2half_rn(v0.y);
    cv.h[2] = __float2half_rn(v0.z); cv.h[3] = __float2half_rn(v0.w);
    cv.h[4] = __float2half_rn(v1.x); cv.h[5] = __float2half_rn(v1.y);
    cv.h[6] = __float2half_rn(v1.z); cv.h[7] = __float2half_rn(v1.w);
    *(uint4*)(g_Xp + (size_t)pos * HID + c) = cv.u;
}

// ---------------------------------------------------------------------------
// combine: out[t] = s0 * O2[pos0] + s1 * O2[pos1]
// ---------------------------------------------------------------------------
__global__ void combine_kernel(float* __restrict__ out) {
    const int t = blockIdx.x;
    const int c = threadIdx.x * 4;
    const int   p0 = g_tok_pos[2 * t],     p1 = g_tok_pos[2 * t + 1];
    const float s0 = g_tok_s[2 * t],       s1 = g_tok_s[2 * t + 1];
    float4 a = *(const float4*)(g_Out2 + (size_t)p0 * HID + c);
    float4 b = *(const float4*)(g_Out2 + (size_t)p1 * HID + c);
    float4 r;
    r.x = s0 * a.x + s1 * b.x;  r.y = s0 * a.y + s1 * b.y;
    r.z = s0 * a.z + s1 * b.z;  r.w = s0 * a.w + s1 * b.w;
    *(float4*)(out + (size_t)t * HID + c) = r;
}

// ---------------------------------------------------------------------------
// tcgen05 / TMA helpers (arch-specific pass only)
// ---------------------------------------------------------------------------
#if USE_TC
__device__ __forceinline__ void mbar_init(uint32_t a, uint32_t c) {
    asm volatile("mbarrier.init.shared.b64 [%0], %1;" :: "r"(a), "r"(c) : "memory");
}
__device__ __forceinline__ void mbar_expect_tx(uint32_t a, uint32_t bytes) {
    asm volatile("mbarrier.arrive.expect_tx.shared.b64 _, [%0], %1;"
                 :: "r"(a), "r"(bytes) : "memory");
}
__device__ __forceinline__ void mbar_wait(uint32_t a, uint32_t par) {
    asm volatile("{\n\t.reg .pred P;\n\tWL_%=:\n\t"
                 "mbarrier.try_wait.parity.acquire.cta.shared::cta.b64 P, [%0], %1, 0x989680;\n\t"
                 "@P bra WD_%=;\n\tbra WL_%=;\n\tWD_%=:\n\t}"
                 :: "r"(a), "r"(par) : "memory");
}
__device__ __forceinline__ void tma_2d(uint32_t dst, const CUtensorMap* map,
                                       int x, int y, uint32_t mbar) {
    asm volatile("cp.async.bulk.tensor.2d.shared::cta.global.tile.mbarrier::complete_tx::bytes "
                 "[%0], [%1, {%2, %3}], [%4];"
                 :: "r"(dst), "l"(map), "r"(x), "r"(y), "r"(mbar) : "memory");
}
__device__ __forceinline__ void tc_alloc(uint32_t slot, uint32_t n) {
    asm volatile("tcgen05.alloc.cta_group::1.sync.aligned.shared::cta.b32 [%0], %1;"
                 :: "r"(slot), "r"(n) : "memory");
}
__device__ __forceinline__ void tc_relinquish() {
    asm volatile("tcgen05.relinquish_alloc_permit.cta_group::1.sync.aligned;");
}
__device__ __forceinline__ void tc_dealloc(uint32_t t, uint32_t n) {
    asm volatile("tcgen05.dealloc.cta_group::1.sync.aligned.b32 %0, %1;" :: "r"(t), "r"(n));
}
__device__ __forceinline__ void tc_commit(uint32_t mbar) {
    asm volatile("tcgen05.commit.cta_group::1.mbarrier::arrive::one.shared::cluster.b64 [%0];"
                 :: "r"(mbar) : "memory");
}
__device__ __forceinline__ void tc_mma_f16_ss(uint32_t d, uint64_t ad, uint64_t bd,
                                              uint32_t idesc, uint32_t en) {
    asm volatile("{\n\t.reg .pred p;\n\tsetp.ne.u32 p, %4, 0;\n\t"
                 "tcgen05.mma.cta_group::1.kind::f16 [%0], %1, %2, %3, {%5,%5,%5,%5}, p;\n\t}"
                 :: "r"(d), "l"(ad), "l"(bd), "r"(idesc), "r"(en), "r"(0u) : "memory");
}
__device__ __forceinline__ void tc_fence_after()  { asm volatile("tcgen05.fence::after_thread_sync;"  ::: "memory"); }
__device__ __forceinline__ void tc_fence_before() { asm volatile("tcgen05.fence::before_thread_sync;" ::: "memory"); }
__device__ __forceinline__ void tc_wait_ld()      { asm volatile("tcgen05.wait::ld.sync.aligned;"     ::: "memory"); }

#define LDTM_X32(r, tmem_addr) \
    asm volatile( \
        "tcgen05.ld.sync.aligned.32x32b.x32.b32 " \
        "{%0, %1, %2, %3, %4, %5, %6, %7, " \
        " %8, %9, %10, %11, %12, %13, %14, %15, " \
        " %16, %17, %18, %19, %20, %21, %22, %23, " \
        " %24, %25, %26, %27, %28, %29, %30, %31}, [%32];" \
        : "=r"((r)[0]),  "=r"((r)[1]),  "=r"((r)[2]),  "=r"((r)[3]), \
          "=r"((r)[4]),  "=r"((r)[5]),  "=r"((r)[6]),  "=r"((r)[7]), \
          "=r"((r)[8]),  "=r"((r)[9]),  "=r"((r)[10]), "=r"((r)[11]), \
          "=r"((r)[12]), "=r"((r)[13]), "=r"((r)[14]), "=r"((r)[15]), \
          "=r"((r)[16]), "=r"((r)[17]), "=r"((r)[18]), "=r"((r)[19]), \
          "=r"((r)[20]), "=r"((r)[21]), "=r"((r)[22]), "=r"((r)[23]), \
          "=r"((r)[24]), "=r"((r)[25]), "=r"((r)[26]), "=r"((r)[27]), \
          "=r"((r)[28]), "=r"((r)[29]), "=r"((r)[30]), "=r"((r)[31]) \
        : "r"(tmem_addr))

// SMEM matrix descriptor: K-major SW128 (LBO=1, SBO=64, version=1, layout=2)
__device__ __forceinline__ uint64_t desc_k(uint32_t a) {
    return 0x4000404000010000ull | ((a >> 4) & 0x3FFF);
}
// idesc kind::f16: c=f32, a/b f16 K-major, M=128, N=128 (validated R10)
#define MMA_IDESC_N128 0x8200010u
#endif // USE_TC

// ---------------------------------------------------------------------------
// Grouped GEMM.  256 threads, BM=128, one N=128 MMA per 64-k chunk.
// TMA-fed: thread 0 issues expect_tx + 2-3 UTMALDG per chunk and all MMAs.
//   MODE 0 (FC1+SwiGLU): grid (32, 32, 8); 64 act cols (proj+gate packed)
//   MODE 1 (FC2):        grid (8, 32, 8);  128 out cols -> g_Out2 fp32
// ---------------------------------------------------------------------------
template <int MODE>
__global__ __launch_bounds__(256)
void moe_gemm_kernel(const __grid_constant__ CUtensorMap tmA,
                     const __grid_constant__ CUtensorMap tmB) {
    const int e   = blockIdx.z;
    const int cnt = g_counts[e];
    const int mt  = blockIdx.y;
    if (mt * 128 >= cnt) return;
    const int bn      = blockIdx.x;
    const int rowbase = g_offsets[e] + mt * 128;
    const int rowlim  = g_offsets[e] + cnt;

    extern __shared__ __align__(1024) char smem[];
    const int tid = threadIdx.x, wid = tid >> 5, lane = tid & 31;

#if USE_TC
    constexpr int K     = MODE ? INTERD : HID;
    constexpr int KT    = K / 64;
    constexpr int ST    = 3;
    constexpr int STAGE = 32768;                      // A 16KB + B 16KB
    constexpr int CTRL  = ST * STAGE;

    uint32_t sbase = (uint32_t)__cvta_generic_to_shared(smem);
    uint32_t barF[ST], barM[ST];
#pragma unroll
    for (int b = 0; b < ST; b++) {
        barF[b] = sbase + CTRL + 8 + b * 8;
        barM[b] = sbase + CTRL + 32 + b * 8;
    }

    if (tid == 0) {
#pragma unroll
        for (int b = 0; b < ST; b++) { mbar_init(barF[b], 1); mbar_init(barM[b], 1); }
    }
    if (wid == 0) { tc_alloc(sbase + CTRL, 128); tc_relinquish(); }
    __syncthreads();
    uint32_t tmem = *(volatile uint32_t*)(smem + CTRL);

    if (tid == 0) {
        // issue TMA for chunk j into stage j%ST
        auto issue = [&](int j) {
            const int s = j % ST;
            const uint32_t stg = sbase + s * STAGE;
            const int k0 = j * 64;
            mbar_expect_tx(barF[s], STAGE);
            tma_2d(stg, &tmA, k0, rowbase, barF[s]);                 // A 128x64 (16KB)
            if (MODE == 0) {                                         // B: proj64 + gate64
                tma_2d(stg + 16384, &tmB, k0, e * 4096 + bn * 64, barF[s]);
                tma_2d(stg + 24576, &tmB, k0, e * 4096 + INTERD + bn * 64, barF[s]);
            } else {                                                 // B: 128 out cols
                tma_2d(stg + 16384, &tmB, k0, e * HID + bn * 128, barF[s]);
            }
        };

        issue(0);
        if (KT > 1) issue(1);
        for (int kt = 0; kt < KT; kt++) {
            const int s = kt % ST;
            const int j = kt + ST - 1;                // keep ST-1 chunks in flight
            if (j < KT) {
                if (kt > 0)                           // stage (j%ST) freed by MMA(kt-1)
                    mbar_wait(barM[(kt - 1) % ST], ((kt - 1) / ST) & 1);
                issue(j);
            }
            mbar_wait(barF[s], (kt / ST) & 1);        // chunk kt data ready
            const uint32_t stg = sbase + s * STAGE;
            uint64_t ad = desc_k(stg);
            uint64_t bd = desc_k(stg + 16384);
#pragma unroll
            for (int k4 = 0; k4 < 4; k4++)
                tc_mma_f16_ss(tmem, ad + 2 * k4, bd + 2 * k4,
                              MMA_IDESC_N128, (kt > 0) || (k4 > 0));
            tc_commit(barM[s]);
        }
        // all MMAs complete when the last commit lands
        mbar_wait(barM[(KT - 1) % ST], ((KT - 1) / ST) & 1);
    }
    __syncthreads();
    tc_fence_after();

    // epilogue: 8 warps; subpartition = wid&3, column-pass = wid>>2
    {
        const int sp = wid & 3, hp = wid >> 2;
        const int m  = rowbase + sp * 32 + lane;
        if (MODE == 0) {
            uint32_t dp[32], dg[32];
            LDTM_X32(dp, tmem + hp * 32);
            LDTM_X32(dg, tmem + 64 + hp * 32);
            tc_wait_ld();
            if (m < rowlim) {
                uint32_t hh[16];
#pragma unroll
                for (int j = 0; j < 32; j += 2) {
                    float p0 = __uint_as_float(dp[j]), p1 = __uint_as_float(dp[j + 1]);
                    float g0 = __uint_as_float(dg[j]), g1 = __uint_as_float(dg[j + 1]);
                    float a0 = p0 * g0 / (1.0f + __expf(-p0));
                    float a1 = p1 * g1 / (1.0f + __expf(-p1));
                    __half2 h = __floats2half2_rn(a0, a1);
                    hh[j >> 1] = *(uint32_t*)&h;
                }
                uint4* dst = (uint4*)(g_Act + (size_t)m * INTERD + bn * 64 + hp * 32);
#pragma unroll
                for (int i = 0; i < 4; i++) dst[i] = ((uint4*)hh)[i];
            }
        } else {
            float* orow = g_Out2 + (size_t)m * HID + bn * 128 + hp * 64;
#pragma unroll
            for (int half = 0; half < 2; half++) {
                uint32_t d[32];
                LDTM_X32(d, tmem + hp * 64 + half * 32);
                tc_wait_ld();
                if (m < rowlim) {
                    uint4* dst = (uint4*)(orow + half * 32);
#pragma unroll
                    for (int i = 0; i < 8; i++) dst[i] = ((uint4*)d)[i];
                }
            }
        }
        tc_fence_before();
    }
    __syncthreads();
    if (wid == 0) tc_dealloc(tmem, 128);

#else
    // ============ naive-correct fallback (insurance only) ============
    (void)smem; (void)wid; (void)lane; (void)tmA; (void)tmB;
    constexpr int K = MODE ? INTERD : HID;
    const __half* Ag = MODE ? g_Act : g_Xp;
    const __half* Wh = MODE ? (g_W2h + (size_t)e * HID * INTERD)
                            : (g_W1h + (size_t)e * 2 * INTERD * HID);
    if (tid >= 128) return;
    const int row = rowbase + tid;
    if (row >= rowlim) return;
    if (MODE == 0) {
        const __half* a = Ag + (size_t)row * K;
        for (int j = 0; j < 64; j++) {
            const __half* wp = Wh + (size_t)(bn * 64 + j) * K;
            const __half* wg = Wh + (size_t)(INTERD + bn * 64 + j) * K;
            float p = 0.0f, g = 0.0f;
            for (int k = 0; k < K; k++) {
                float av = __half2float(a[k]);
                p += av * __half2float(wp[k]);
                g += av * __half2float(wg[k]);
            }
            float act = p / (1.0f + __expf(-p)) * g;
            g_Act[(size_t)row * INTERD + bn * 64 + j] = __float2half_rn(act);
        }
    } else {
        const __half* a = Ag + (size_t)row * K;
        for (int j = 0; j < 128; j++) {
            const __half* wp = Wh + (size_t)(bn * 128 + j) * K;
            float s = 0.0f;
            for (int k = 0; k < K; k++)
                s += __half2float(a[k]) * __half2float(wp[k]);
            g_Out2[(size_t)row * HID + bn * 128 + j] = s;
        }
    }
#endif // USE_TC
}

// ---------------------------------------------------------------------------
// host: tensor map construction via runtime-fetched driver entry point
// ---------------------------------------------------------------------------
typedef CUresult (*PFN_encodeTiled)(
    CUtensorMap*, CUtensorMapDataType, cuuint32_t, void*,
    const cuuint64_t*, const cuuint64_t*, const cuuint32_t*, const cuuint32_t*,
    CUtensorMapInterleave, CUtensorMapSwizzle, CUtensorMapL2promotion,
    CUtensorMapFloatOOBfill);

static void make_map_2d(PFN_encodeTiled enc, CUtensorMap* m, void* base,
                        uint64_t dim0, uint64_t dim1, uint32_t box0, uint32_t box1) {
    cuuint64_t dims[2]    = {dim0, dim1};
    cuuint64_t strides[1] = {dim0 * 2};               // fp16 bytes per row
    cuuint32_t box[2]     = {box0, box1};
    cuuint32_t elem[2]    = {1, 1};
    enc(m, CU_TENSOR_MAP_DATA_TYPE_FLOAT16, 2, base, dims, strides, box, elem,
        CU_TENSOR_MAP_INTERLEAVE_NONE, CU_TENSOR_MAP_SWIZZLE_128B,
        CU_TENSOR_MAP_L2_PROMOTION_L2_128B, CU_TENSOR_MAP_FLOAT_OOB_FILL_NONE);
}

extern "C" void kernel_launch(void* const* d_in, const int* in_sizes, int n_in,
                              void* d_out, int out_size) {
    const float* X      = (const float*)d_in[0];  // [2048,1024]
    const float* logits = (const float*)d_in[1];  // [2048,8]
    const float* w1     = (const float*)d_in[2];  // [8,1024,4096]
    const float* w2     = (const float*)d_in[3];  // [8,2048,1024]
    float* out          = (float*)d_out;          // [2048,1024]

    void *xp = nullptr, *act = nullptr, *w1h = nullptr, *w2h = nullptr;
    cudaGetSymbolAddress(&xp,  g_Xp);
    cudaGetSymbolAddress(&act, g_Act);
    cudaGetSymbolAddress(&w1h, g_W1h);
    cudaGetSymbolAddress(&w2h, g_W2h);

    // tensor maps (CPU-side; capture-safe)
    void* pfn = nullptr;
    cudaDriverEntryPointQueryResult qr;
    cudaGetDriverEntryPoint("cuTensorMapEncodeTiled", &pfn, cudaEnableDefault, &qr);
    PFN_encodeTiled enc = (PFN_encodeTiled)pfn;
    CUtensorMap mXP, mW1, mACT, mW2;
    make_map_2d(enc, &mXP,  xp,  HID,    NPP,             64, 128);
    make_map_2d(enc, &mW1,  w1h, HID,    NE * 2 * INTERD, 64, 64);
    make_map_2d(enc, &mACT, act, INTERD, NPP,             64, 128);
    make_map_2d(enc, &mW2,  w2h, INTERD, NE * HID,        64, 128);

    constexpr int SMEM = 3 * 32768 + 64;          // 98368 -> 2 CTAs/SM
    cudaFuncSetAttribute(moe_gemm_kernel<0>, cudaFuncAttributeMaxDynamicSharedMemorySize, SMEM);
    cudaFuncSetAttribute(moe_gemm_kernel<1>, cudaFuncAttributeMaxDynamicSharedMemorySize, SMEM);

    // 0: conv w1 (+ zero routing counters)
    convT_kernel<<<dim3(128, 32, NE), dim3(32, 8)>>>(w1, (__half*)w1h, HID, 2 * INTERD, 1, 0, logits);
    // 1: conv w2 (+ top-2 routing in blocks x==0,y==0)
    convT_kernel<<<dim3(32, 64, NE), dim3(32, 8)>>>(w2, (__half*)w2h, INTERD, HID, 0, 1, logits);
    // 2: scatter + permute (one block per pair)
    scatter_permute_kernel<<<NP, 128>>>(X);
    // 3: FC1 (+SwiGLU) — ncu-profiled slot
    moe_gemm_kernel<0><<<dim3(32, 32, NE), 256, SMEM>>>(mXP, mW1);
    // 4: FC2 -> g_Out2
    moe_gemm_kernel<1><<<dim3(8, 32, NE), 256, SMEM>>>(mACT, mW2);
    // 5: weighted combine
    combine_kernel<<<NT, 256>>>(out);
}

// round 13
// speedup vs baseline: 1.3751x; 1.0886x over previous
#include <cuda_runtime.h>
#include <cuda_fp16.h>
#include <cuda.h>
#include <cstdint>

// ---------------------------------------------------------------------------
// MoE (AriaExperts): top-2 routing + grouped tcgen05 f16 GEMM (SwiGLU fused)
// tokens=2048, hidden=1024, inter=2048, experts=8, topk=2
//
// R13: R12 warp-specialized mainloop (thread 0 = TMA producer, thread 32 =
// MMA consumer, commit->empty backpressure) with the FIXED end-of-loop
// handshake: the producer extends its sequential (alias-free) wait chain on
// the empty barriers through the final ST commits, then __syncthreads()
// releases the epilogue. (R12's cold parity wait aliased -> read garbage.)
// ---------------------------------------------------------------------------

#if defined(__CUDA_ARCH__) && \
    (defined(__CUDA_ARCH_FEAT_SM103_ALL) || \
     (defined(__CUDA_ARCH_SPECIFIC__)) || \
     (defined(__CUDA_ARCH_FAMILY_SPECIFIC__)))
#define USE_TC 1
#else
#define USE_TC 0
#endif

#define NT     2048
#define HID    1024
#define INTERD 2048
#define NE     8
#define TK     2
#define NP     (NT*TK)
#define NPP    (NP + 256)

// ---- device scratch ----
__device__ __align__(16) __half g_Xp  [NPP * HID];
__device__ __align__(16) __half g_Act [NPP * INTERD];
__device__ __align__(16) float  g_Out2[NPP * HID];
__device__ __align__(16) __half g_W1h[NE * 2 * INTERD * HID];   // [E][4096][1024] k-contig
__device__ __align__(16) __half g_W2h[NE * HID * INTERD];       // [E][1024][2048] k-contig
__device__ int   g_counts[NE];
__device__ int   g_fill[NE];
__device__ int   g_offsets[NE + 1];
__device__ int   g_tok_e[NT * TK];
__device__ float g_tok_s[NT * TK];
__device__ int   g_tok_pos[NT * TK];

// ---------------------------------------------------------------------------
// conv: weight transpose + fp32->fp16  (in [e][K][N] f32 -> out [e][N][K] f16)
// 64k x 32n tiles, 256 threads; half2 stores -> fully coalesced both sides.
// ---------------------------------------------------------------------------
__global__ void convT_kernel(const float* __restrict__ in, __half* __restrict__ out,
                             int K, int N, int zeroFlag, int routeFlag,
                             const float* __restrict__ logits) {
    __shared__ float tile[64][33];
    const int e  = blockIdx.z;
    const int n0 = blockIdx.x * 32, k0 = blockIdx.y * 64;
    const float* ip = in  + (size_t)e * K * N;
    __half*      op = out + (size_t)e * N * K;
    const int tid = threadIdx.x;
#pragma unroll
    for (int i = 0; i < 8; i++) {
        int idx = i * 256 + tid, kk = idx >> 5, nn = idx & 31;
        tile[kk][nn] = ip[(size_t)(k0 + kk) * N + n0 + nn];
    }
    __syncthreads();
#pragma unroll
    for (int i = 0; i < 4; i++) {
        int idx = i * 256 + tid, nn = idx >> 5, kx = idx & 31;
        __half2 h = __floats2half2_rn(tile[2 * kx][nn], tile[2 * kx + 1][nn]);
        *(__half2*)(op + (size_t)(n0 + nn) * K + k0 + 2 * kx) = h;
    }

    if (zeroFlag && blockIdx.x == 0 && blockIdx.y == 0 && blockIdx.z == 0 && tid == 0) {
#pragma unroll
        for (int i = 0; i < NE; i++) { g_counts[i] = 0; g_fill[i] = 0; }
    }
    if (routeFlag && blockIdx.x == 0 && blockIdx.y == 0) {
        int t = blockIdx.z * 256 + tid;
        float l[NE];
#pragma unroll
        for (int i = 0; i < NE; i++) l[i] = logits[t * NE + i];
        int b0 = 0; float v0 = l[0];
#pragma unroll
        for (int i = 1; i < NE; i++) if (l[i] > v0) { v0 = l[i]; b0 = i; }
        int b1 = -1; float v1 = -1e30f;
#pragma unroll
        for (int i = 0; i < NE; i++) if (i != b0 && l[i] > v1) { v1 = l[i]; b1 = i; }
        float e1  = __expf(v1 - v0);
        float inv = 1.0f / (1.0f + e1);
        g_tok_e[t * 2 + 0] = b0; g_tok_s[t * 2 + 0] = inv;
        g_tok_e[t * 2 + 1] = b1; g_tok_s[t * 2 + 1] = e1 * inv;
        atomicAdd(&g_counts[b0], 1);
        atomicAdd(&g_counts[b1], 1);
    }
}

// ---------------------------------------------------------------------------
// scatter + permute: one block per token-expert pair.
// ---------------------------------------------------------------------------
__global__ void scatter_permute_kernel(const float* __restrict__ X) {
    __shared__ int s_pos;
    const int p = blockIdx.x;
    const int t = p >> 1;
    if (threadIdx.x == 0) {
        int e = g_tok_e[p];
        int s = 0, off = 0;
#pragma unroll
        for (int i = 0; i < NE; i++) { if (i == e) off = s; s += g_counts[i]; }
        int pos = off + atomicAdd(&g_fill[e], 1);
        g_tok_pos[p] = pos;
        s_pos = pos;
        if (p == 0) {
            int s2 = 0;
#pragma unroll
            for (int i = 0; i < NE; i++) { g_offsets[i] = s2; s2 += g_counts[i]; }
            g_offsets[NE] = s2;
        }
    }
    __syncthreads();
    const int pos = s_pos;
    const int c = threadIdx.x * 8;
    const float4* s = (const float4*)(X + (size_t)t * HID + c);
    float4 v0 = s[0], v1 = s[1];
    union { __half h[8]; uint4 u; } cv;
    cv.h[0] = __float2half_rn(v0.x); cv.h[1] = __float2half_rn(v0.y);
    cv.h[2] = __float2half_rn(v0.z); cv.h[3] = __float2half_rn(v0.w);
    cv.h[4] = __float2half_rn(v1.x); cv.h[5] = __float2half_rn(v1.y);
    cv.h[6] = __float2half_rn(v1.z); cv.h[7] = __float2half_rn(v1.w);
    *(uint4*)(g_Xp + (size_t)pos * HID + c) = cv.u;
}

// ---------------------------------------------------------------------------
// combine: out[t] = s0 * O2[pos0] + s1 * O2[pos1]
// ---------------------------------------------------------------------------
__global__ void combine_kernel(float* __restrict__ out) {
    const int t = blockIdx.x;
    const int c = threadIdx.x * 4;
    const int   p0 = g_tok_pos[2 * t],     p1 = g_tok_pos[2 * t + 1];
    const float s0 = g_tok_s[2 * t],       s1 = g_tok_s[2 * t + 1];
    float4 a = *(const float4*)(g_Out2 + (size_t)p0 * HID + c);
    float4 b = *(const float4*)(g_Out2 + (size_t)p1 * HID + c);
    float4 r;
    r.x = s0 * a.x + s1 * b.x;  r.y = s0 * a.y + s1 * b.y;
    r.z = s0 * a.z + s1 * b.z;  r.w = s0 * a.w + s1 * b.w;
    *(float4*)(out + (size_t)t * HID + c) = r;
}

// ---------------------------------------------------------------------------
// tcgen05 / TMA helpers (arch-specific pass only)
// ---------------------------------------------------------------------------
#if USE_TC
__device__ __forceinline__ void mbar_init(uint32_t a, uint32_t c) {
    asm volatile("mbarrier.init.shared.b64 [%0], %1;" :: "r"(a), "r"(c) : "memory");
}
__device__ __forceinline__ void mbar_expect_tx(uint32_t a, uint32_t bytes) {
    asm volatile("mbarrier.arrive.expect_tx.shared.b64 _, [%0], %1;"
                 :: "r"(a), "r"(bytes) : "memory");
}
__device__ __forceinline__ void mbar_wait(uint32_t a, uint32_t par) {
    asm volatile("{\n\t.reg .pred P;\n\tWL_%=:\n\t"
                 "mbarrier.try_wait.parity.acquire.cta.shared::cta.b64 P, [%0], %1, 0x989680;\n\t"
                 "@P bra WD_%=;\n\tbra WL_%=;\n\tWD_%=:\n\t}"
                 :: "r"(a), "r"(par) : "memory");
}
__device__ __forceinline__ void tma_2d(uint32_t dst, const CUtensorMap* map,
                                       int x, int y, uint32_t mbar) {
    asm volatile("cp.async.bulk.tensor.2d.shared::cta.global.tile.mbarrier::complete_tx::bytes "
                 "[%0], [%1, {%2, %3}], [%4];"
                 :: "r"(dst), "l"(map), "r"(x), "r"(y), "r"(mbar) : "memory");
}
__device__ __forceinline__ void tc_alloc(uint32_t slot, uint32_t n) {
    asm volatile("tcgen05.alloc.cta_group::1.sync.aligned.shared::cta.b32 [%0], %1;"
                 :: "r"(slot), "r"(n) : "memory");
}
__device__ __forceinline__ void tc_relinquish() {
    asm volatile("tcgen05.relinquish_alloc_permit.cta_group::1.sync.aligned;");
}
__device__ __forceinline__ void tc_dealloc(uint32_t t, uint32_t n) {
    asm volatile("tcgen05.dealloc.cta_group::1.sync.aligned.b32 %0, %1;" :: "r"(t), "r"(n));
}
__device__ __forceinline__ void tc_commit(uint32_t mbar) {
    asm volatile("tcgen05.commit.cta_group::1.mbarrier::arrive::one.shared::cluster.b64 [%0];"
                 :: "r"(mbar) : "memory");
}
__device__ __forceinline__ void tc_mma_f16_ss(uint32_t d, uint64_t ad, uint64_t bd,
                                              uint32_t idesc, uint32_t en) {
    asm volatile("{\n\t.reg .pred p;\n\tsetp.ne.u32 p, %4, 0;\n\t"
                 "tcgen05.mma.cta_group::1.kind::f16 [%0], %1, %2, %3, {%5,%5,%5,%5}, p;\n\t}"
                 :: "r"(d), "l"(ad), "l"(bd), "r"(idesc), "r"(en), "r"(0u) : "memory");
}
__device__ __forceinline__ void tc_fence_after()  { asm volatile("tcgen05.fence::after_thread_sync;"  ::: "memory"); }
__device__ __forceinline__ void tc_fence_before() { asm volatile("tcgen05.fence::before_thread_sync;" ::: "memory"); }
__device__ __forceinline__ void tc_wait_ld()      { asm volatile("tcgen05.wait::ld.sync.aligned;"     ::: "memory"); }

#define LDTM_X32(r, tmem_addr) \
    asm volatile( \
        "tcgen05.ld.sync.aligned.32x32b.x32.b32 " \
        "{%0, %1, %2, %3, %4, %5, %6, %7, " \
        " %8, %9, %10, %11, %12, %13, %14, %15, " \
        " %16, %17, %18, %19, %20, %21, %22, %23, " \
        " %24, %25, %26, %27, %28, %29, %30, %31}, [%32];" \
        : "=r"((r)[0]),  "=r"((r)[1]),  "=r"((r)[2]),  "=r"((r)[3]), \
          "=r"((r)[4]),  "=r"((r)[5]),  "=r"((r)[6]),  "=r"((r)[7]), \
          "=r"((r)[8]),  "=r"((r)[9]),  "=r"((r)[10]), "=r"((r)[11]), \
          "=r"((r)[12]), "=r"((r)[13]), "=r"((r)[14]), "=r"((r)[15]), \
          "=r"((r)[16]), "=r"((r)[17]), "=r"((r)[18]), "=r"((r)[19]), \
          "=r"((r)[20]), "=r"((r)[21]), "=r"((r)[22]), "=r"((r)[23]), \
          "=r"((r)[24]), "=r"((r)[25]), "=r"((r)[26]), "=r"((r)[27]), \
          "=r"((r)[28]), "=r"((r)[29]), "=r"((r)[30]), "=r"((r)[31]) \
        : "r"(tmem_addr))

// SMEM matrix descriptor: K-major SW128 (LBO=1, SBO=64, version=1, layout=2)
__device__ __forceinline__ uint64_t desc_k(uint32_t a) {
    return 0x4000404000010000ull | ((a >> 4) & 0x3FFF);
}
// idesc kind::f16: c=f32, a/b f16 K-major, M=128, N=128 (validated R10/R11)
#define MMA_IDESC_N128 0x8200010u
#endif // USE_TC

// ---------------------------------------------------------------------------
// Grouped GEMM. 256 threads, BM=128, one N=128 MMA per 64-k chunk.
// Warp-specialized: thread 0 = TMA producer, thread 32 = MMA consumer.
// Producer's empty-wait chain is extended past the loop to observe the final
// ST commits, then __syncthreads() gates the epilogue (fixes R12 race).
//   MODE 0 (FC1+SwiGLU): grid (32, 32, 8); 64 act cols (proj+gate packed)
//   MODE 1 (FC2):        grid (8, 32, 8);  128 out cols -> g_Out2 fp32
// ---------------------------------------------------------------------------
template <int MODE>
__global__ __launch_bounds__(256)
void moe_gemm_kernel(const __grid_constant__ CUtensorMap tmA,
                     const __grid_constant__ CUtensorMap tmB) {
    const int e   = blockIdx.z;
    const int cnt = g_counts[e];
    const int mt  = blockIdx.y;
    if (mt * 128 >= cnt) return;
    const int bn      = blockIdx.x;
    const int rowbase = g_offsets[e] + mt * 128;
    const int rowlim  = g_offsets[e] + cnt;

    extern __shared__ __align__(1024) char smem[];
    const int tid = threadIdx.x, wid = tid >> 5, lane = tid & 31;

#if USE_TC
    constexpr int K     = MODE ? INTERD : HID;
    constexpr int KT    = K / 64;
    constexpr int ST    = 3;
    constexpr int STAGE = 32768;                      // A 16KB + B 16KB
    constexpr int CTRL  = ST * STAGE;

    uint32_t sbase = (uint32_t)__cvta_generic_to_shared(smem);
    uint32_t barF[ST], barE[ST];
#pragma unroll
    for (int b = 0; b < ST; b++) {
        barF[b] = sbase + CTRL + 8 + b * 8;           // full: TMA complete_tx
        barE[b] = sbase + CTRL + 32 + b * 8;          // empty: tcgen05.commit
    }

    if (tid == 0) {
#pragma unroll
        for (int b = 0; b < ST; b++) { mbar_init(barF[b], 1); mbar_init(barE[b], 1); }
    }
    if (wid == 0) { tc_alloc(sbase + CTRL, 128); tc_relinquish(); }
    __syncthreads();
    uint32_t tmem = *(volatile uint32_t*)(smem + CTRL);

    if (tid == 0) {
        // ---- producer: TMA issue, gated on stage-empty (commit arrivals) ----
        for (int j = 0; j < KT; j++) {
            const int s = j % ST;
            if (j >= ST) mbar_wait(barE[s], ((j / ST) - 1) & 1);
            const uint32_t stg = sbase + s * STAGE;
            const int k0 = j * 64;
            mbar_expect_tx(barF[s], STAGE);
            tma_2d(stg, &tmA, k0, rowbase, barF[s]);                 // A 128x64
            if (MODE == 0) {                                         // B: proj64 + gate64
                tma_2d(stg + 16384, &tmB, k0, e * 4096 + bn * 64, barF[s]);
                tma_2d(stg + 24576, &tmB, k0, e * 4096 + INTERD + bn * 64, barF[s]);
            } else {                                                 // B: 128 out cols
                tma_2d(stg + 16384, &tmB, k0, e * HID + bn * 128, barF[s]);
            }
        }
        // ---- tail: extend the sequential wait chain through the final
        //      ST commits (kt = KT-ST .. KT-1). Same formula -> alias-free.
        for (int jj = KT; jj < KT + ST; jj++)
            mbar_wait(barE[jj % ST], ((jj / ST) - 1) & 1);
    } else if (tid == 32) {
        // ---- consumer: MMA issue, gated on stage-full; commit -> empty ----
        for (int kt = 0; kt < KT; kt++) {
            const int s = kt % ST;
            mbar_wait(barF[s], (kt / ST) & 1);
            const uint32_t stg = sbase + s * STAGE;
            uint64_t ad = desc_k(stg);
            uint64_t bd = desc_k(stg + 16384);
#pragma unroll
            for (int k4 = 0; k4 < 4; k4++)
                tc_mma_f16_ss(tmem, ad + 2 * k4, bd + 2 * k4,
                              MMA_IDESC_N128, (kt > 0) || (k4 > 0));
            tc_commit(barE[s]);
        }
    }
    // thread 0 arrives only after observing ALL commits complete -> epilogue safe
    __syncthreads();
    tc_fence_after();

    // epilogue: 8 warps; subpartition = wid&3, column-pass = wid>>2
    {
        const int sp = wid & 3, hp = wid >> 2;
        const int m  = rowbase + sp * 32 + lane;
        if (MODE == 0) {
            uint32_t dp[32], dg[32];
            LDTM_X32(dp, tmem + hp * 32);
            LDTM_X32(dg, tmem + 64 + hp * 32);
            tc_wait_ld();
            if (m < rowlim) {
                uint32_t hh[16];
#pragma unroll
                for (int j = 0; j < 32; j += 2) {
                    float p0 = __uint_as_float(dp[j]), p1 = __uint_as_float(dp[j + 1]);
                    float g0 = __uint_as_float(dg[j]), g1 = __uint_as_float(dg[j + 1]);
                    float a0 = p0 * g0 / (1.0f + __expf(-p0));
                    float a1 = p1 * g1 / (1.0f + __expf(-p1));
                    __half2 h = __floats2half2_rn(a0, a1);
                    hh[j >> 1] = *(uint32_t*)&h;
                }
                uint4* dst = (uint4*)(g_Act + (size_t)m * INTERD + bn * 64 + hp * 32);
#pragma unroll
                for (int i = 0; i < 4; i++) dst[i] = ((uint4*)hh)[i];
            }
        } else {
            float* orow = g_Out2 + (size_t)m * HID + bn * 128 + hp * 64;
#pragma unroll
            for (int half = 0; half < 2; half++) {
                uint32_t d[32];
                LDTM_X32(d, tmem + hp * 64 + half * 32);
                tc_wait_ld();
                if (m < rowlim) {
                    uint4* dst = (uint4*)(orow + half * 32);
#pragma unroll
                    for (int i = 0; i < 8; i++) dst[i] = ((uint4*)d)[i];
                }
            }
        }
        tc_fence_before();
    }
    __syncthreads();
    if (wid == 0) tc_dealloc(tmem, 128);

#else
    // ============ naive-correct fallback (insurance only) ============
    (void)smem; (void)wid; (void)lane; (void)tmA; (void)tmB;
    constexpr int K = MODE ? INTERD : HID;
    const __half* Ag = MODE ? g_Act : g_Xp;
    const __half* Wh = MODE ? (g_W2h + (size_t)e * HID * INTERD)
                            : (g_W1h + (size_t)e * 2 * INTERD * HID);
    if (tid >= 128) return;
    const int row = rowbase + tid;
    if (row >= rowlim) return;
    if (MODE == 0) {
        const __half* a = Ag + (size_t)row * K;
        for (int j = 0; j < 64; j++) {
            const __half* wp = Wh + (size_t)(bn * 64 + j) * K;
            const __half* wg = Wh + (size_t)(INTERD + bn * 64 + j) * K;
            float p = 0.0f, g = 0.0f;
            for (int k = 0; k < K; k++) {
                float av = __half2float(a[k]);
                p += av * __half2float(wp[k]);
                g += av * __half2float(wg[k]);
            }
            float act = p / (1.0f + __expf(-p)) * g;
            g_Act[(size_t)row * INTERD + bn * 64 + j] = __float2half_rn(act);
        }
    } else {
        const __half* a = Ag + (size_t)row * K;
        for (int j = 0; j < 128; j++) {
            const __half* wp = Wh + (size_t)(bn * 128 + j) * K;
            float s = 0.0f;
            for (int k = 0; k < K; k++)
                s += __half2float(a[k]) * __half2float(wp[k]);
            g_Out2[(size_t)row * HID + bn * 128 + j] = s;
        }
    }
#endif // USE_TC
}

// ---------------------------------------------------------------------------
// host: tensor map construction via runtime-fetched driver entry point
// ---------------------------------------------------------------------------
typedef CUresult (*PFN_encodeTiled)(
    CUtensorMap*, CUtensorMapDataType, cuuint32_t, void*,
    const cuuint64_t*, const cuuint64_t*, const cuuint32_t*, const cuuint32_t*,
    CUtensorMapInterleave, CUtensorMapSwizzle, CUtensorMapL2promotion,
    CUtensorMapFloatOOBfill);

static void make_map_2d(PFN_encodeTiled enc, CUtensorMap* m, void* base,
                        uint64_t dim0, uint64_t dim1, uint32_t box0, uint32_t box1) {
    cuuint64_t dims[2]    = {dim0, dim1};
    cuuint64_t strides[1] = {dim0 * 2};               // fp16 bytes per row
    cuuint32_t box[2]     = {box0, box1};
    cuuint32_t elem[2]    = {1, 1};
    enc(m, CU_TENSOR_MAP_DATA_TYPE_FLOAT16, 2, base, dims, strides, box, elem,
        CU_TENSOR_MAP_INTERLEAVE_NONE, CU_TENSOR_MAP_SWIZZLE_128B,
        CU_TENSOR_MAP_L2_PROMOTION_L2_128B, CU_TENSOR_MAP_FLOAT_OOB_FILL_NONE);
}

extern "C" void kernel_launch(void* const* d_in, const int* in_sizes, int n_in,
                              void* d_out, int out_size) {
    const float* X      = (const float*)d_in[0];  // [2048,1024]
    const float* logits = (const float*)d_in[1];  // [2048,8]
    const float* w1     = (const float*)d_in[2];  // [8,1024,4096]
    const float* w2     = (const float*)d_in[3];  // [8,2048,1024]
    float* out          = (float*)d_out;          // [2048,1024]

    void *xp = nullptr, *act = nullptr, *w1h = nullptr, *w2h = nullptr;
    cudaGetSymbolAddress(&xp,  g_Xp);
    cudaGetSymbolAddress(&act, g_Act);
    cudaGetSymbolAddress(&w1h, g_W1h);
    cudaGetSymbolAddress(&w2h, g_W2h);

    void* pfn = nullptr;
    cudaDriverEntryPointQueryResult qr;
    cudaGetDriverEntryPoint("cuTensorMapEncodeTiled", &pfn, cudaEnableDefault, &qr);
    PFN_encodeTiled enc = (PFN_encodeTiled)pfn;
    CUtensorMap mXP, mW1, mACT, mW2;
    make_map_2d(enc, &mXP,  xp,  HID,    NPP,             64, 128);
    make_map_2d(enc, &mW1,  w1h, HID,    NE * 2 * INTERD, 64, 64);
    make_map_2d(enc, &mACT, act, INTERD, NPP,             64, 128);
    make_map_2d(enc, &mW2,  w2h, INTERD, NE * HID,        64, 128);

    constexpr int SMEM = 3 * 32768 + 64;          // 98368 -> 2 CTAs/SM
    cudaFuncSetAttribute(moe_gemm_kernel<0>, cudaFuncAttributeMaxDynamicSharedMemorySize, SMEM);
    cudaFuncSetAttribute(moe_gemm_kernel<1>, cudaFuncAttributeMaxDynamicSharedMemorySize, SMEM);

    // 0: conv w1 (+ zero routing counters)
    convT_kernel<<<dim3(128, 16, NE), 256>>>(w1, (__half*)w1h, HID, 2 * INTERD, 1, 0, logits);
    // 1: conv w2 (+ top-2 routing in blocks x==0,y==0)
    convT_kernel<<<dim3(32, 32, NE), 256>>>(w2, (__half*)w2h, INTERD, HID, 0, 1, logits);
    // 2: scatter + permute (one block per pair)
    scatter_permute_kernel<<<NP, 128>>>(X);
    // 3: FC1 (+SwiGLU) — ncu-profiled slot
    moe_gemm_kernel<0><<<dim3(32, 32, NE), 256, SMEM>>>(mXP, mW1);
    // 4: FC2 -> g_Out2
    moe_gemm_kernel<1><<<dim3(8, 32, NE), 256, SMEM>>>(mACT, mW2);
    // 5: weighted combine
    combine_kernel<<<NT, 256>>>(out);
}